// round 10
// baseline (speedup 1.0000x reference)
#include <cuda_runtime.h>
#include <cuda_fp16.h>
#include <math.h>
#include <math_constants.h>
#include <stdint.h>

#define NPTS 6000
#define DIM  1024
#define K3   3072
#define NG   16
#define DG   64
#define KSEL 300

// ---------------- scratch (device globals; no allocation allowed) ----------------
static __device__ float g_norms[NPTS];
static __device__ float g_Drec[(size_t)NPTS * NPTS];          // 144 MB
static __device__ int   g_idx[KSEL];
static __device__ float g_q[KSEL * DIM];
static __device__ float g_kk[(size_t)NPTS * DIM];
static __device__ float g_V[(size_t)NPTS * DIM];
static __device__ float g_W[(size_t)KSEL * NG * NPTS];        // 115 MB logits/soft
static __device__ __half g_Xa[(size_t)NPTS * K3];             // [h | l | h]
static __device__ __half g_Xb[(size_t)NPTS * K3];             // [h | h | l]
static __device__ __half g_Wqs[(size_t)DIM * K3];             // [h | h | l]
static __device__ __half g_Wks[(size_t)DIM * K3];
static __device__ __half g_Wvs[(size_t)DIM * K3];
static __device__ int    g_cnt[4];                            // gross, moderate, first_m, spare
static __device__ volatile float g_sink;

__device__ __forceinline__ uint32_t smem_u32(const void* p) {
    uint32_t a;
    asm("{ .reg .u64 t; cvta.to.shared.u64 t, %1; cvt.u32.u64 %0, t; }" : "=r"(a) : "l"(p));
    return a;
}
#define CP_ASYNC16(dst, src) \
    asm volatile("cp.async.cg.shared.global [%0], [%1], 16;" :: "r"(dst), "l"(src))
#define CP_COMMIT() asm volatile("cp.async.commit_group;")
#define CP_WAIT1()  asm volatile("cp.async.wait_group 1;")
#define CP_WAIT0()  asm volatile("cp.async.wait_group 0;")
#define LDMATRIX_X4(r0, r1, r2, r3, a) \
    asm volatile("ldmatrix.sync.aligned.m8n8.x4.shared.b16 {%0,%1,%2,%3}, [%4];" \
        : "=r"(r0), "=r"(r1), "=r"(r2), "=r"(r3) : "r"(a))
#define MMA16816(c, a, b0, b1) \
    asm volatile("mma.sync.aligned.m16n8k16.row.col.f32.f16.f16.f32 " \
        "{%0,%1,%2,%3}, {%4,%5,%6,%7}, {%8,%9}, {%0,%1,%2,%3};" \
        : "+f"((c)[0]), "+f"((c)[1]), "+f"((c)[2]), "+f"((c)[3]) \
        : "r"((a)[0]), "r"((a)[1]), "r"((a)[2]), "r"((a)[3]), "r"(b0), "r"(b1))

// ---------------- counters reset ----------------
__global__ void zero_cnt_kernel() {
    if (threadIdx.x == 0) {
        g_cnt[0] = 0; g_cnt[1] = 0; g_cnt[2] = 0x7fffffff; g_cnt[3] = 0;
    }
}

// ---------------- diagnostic probe: dur encodes counters -------------------------
__global__ void probe_kernel() {
    long n = 0;
    if (g_cnt[0] > 0) n += 2000000;   // gross mismatches  -> ~+4.4 ms
    if (g_cnt[1] > 0) n += 500000;    // moderate          -> ~+1.1 ms
    float x = 1.0f;
    for (long i = 0; i < n; i++) x = fmaf(x, 1.0000001f, 1e-9f);
    if (x == 12345.678f) g_sink = x;
}

// ---------------- 3-term fp16 split --------------------------------------------
__global__ __launch_bounds__(256) void split3_kernel(const float* __restrict__ X,
                                                     __half* __restrict__ Xa,
                                                     __half* __restrict__ Xb,
                                                     int rows) {
    size_t i = (size_t)blockIdx.x * 256 + threadIdx.x;
    if (i >= (size_t)rows * DIM) return;
    size_t r = i / DIM, c = i % DIM;
    float x = X[i];
    __half h = __float2half(x);
    __half l = __float2half(x - __half2float(h));
    if (Xa) {
        Xa[r * K3 + c]            = h;
        Xa[r * K3 + DIM + c]      = l;
        Xa[r * K3 + 2 * DIM + c]  = h;
    }
    if (Xb) {
        Xb[r * K3 + c]            = h;
        Xb[r * K3 + DIM + c]      = h;
        Xb[r * K3 + 2 * DIM + c]  = l;
    }
}

// ---------------- row squared-norms ----------------
__global__ __launch_bounds__(256) void norms_kernel(const float* __restrict__ X) {
    int r = blockIdx.x;
    const float* x = X + (size_t)r * DIM;
    float s = 0.f;
    for (int c = threadIdx.x; c < DIM; c += 256) { float v = x[c]; s = fmaf(v, v, s); }
    __shared__ float sred[8];
    for (int o = 16; o > 0; o >>= 1) s += __shfl_down_sync(0xffffffffu, s, o);
    if ((threadIdx.x & 31) == 0) sred[threadIdx.x >> 5] = s;
    __syncthreads();
    if (threadIdx.x == 0) {
        float t = 0.f;
        for (int i = 0; i < 8; i++) t += sred[i];
        g_norms[r] = t;
    }
}

// =============== fp16 HMMA GEMM (R8-proven): C = A(M,3072)·B(Nn,3072)^T + bias ===============
#define BK 64
#define NC (K3 / BK)
#define SROW 144
#define STAGE_BYTES (2 * 128 * SROW)
#define GSMEM (2 * STAGE_BYTES)

__global__ __launch_bounds__(256) void mma_gemm_kernel(
    const __half* __restrict__ A, const __half* __restrict__ B,
    float* __restrict__ C, int M, int Nn,
    const float* __restrict__ bias, const int* __restrict__ rowIdx, int symSkip)
{
    if (symSkip && (int)blockIdx.x < (int)blockIdx.y) return;
    extern __shared__ char smem[];
    const uint32_t sb = smem_u32(smem);
    const int tid = threadIdx.x;
    const int wid = tid >> 5;
    const int lid = tid & 31;
    const int bm = blockIdx.y * 128;
    const int bn = blockIdx.x * 128;

    const __half* gsrc[8];
    uint32_t sdst[8];
#pragma unroll
    for (int i = 0; i < 8; i++) {
        int u = tid + i * 256;
        int mat = u >> 10;
        int r = (u >> 3) & 127;
        int q = u & 7;
        int grow;
        if (mat == 0) {
            grow = bm + r; if (grow > M - 1) grow = M - 1;
            if (rowIdx) grow = rowIdx[grow];
            gsrc[i] = A + (size_t)grow * K3 + q * 8;
        } else {
            grow = bn + r; if (grow > Nn - 1) grow = Nn - 1;
            gsrc[i] = B + (size_t)grow * K3 + q * 8;
        }
        sdst[i] = sb + (uint32_t)(mat * 128 * SROW + r * SROW + q * 16);
    }

#pragma unroll
    for (int i = 0; i < 8; i++) CP_ASYNC16(sdst[i], gsrc[i]);
    CP_COMMIT();
#pragma unroll
    for (int i = 0; i < 8; i++) CP_ASYNC16(sdst[i] + STAGE_BYTES, gsrc[i] + BK);
    CP_COMMIT();

    const int wm = (wid >> 2) * 64;
    const int wn = (wid & 3) * 32;
    float c[4][4][4] = {};

    const uint32_t aAddrBase = sb + (uint32_t)((wm + (lid & 15)) * SROW + (lid >> 4) * 16);
    const uint32_t bAddrBase = sb + (uint32_t)(128 * SROW + (wn + (lid >> 4) * 8 + (lid & 7)) * SROW + ((lid >> 3) & 1) * 16);

    for (int kc = 0; kc < NC; kc++) {
        if (kc == NC - 1) { CP_WAIT0(); } else { CP_WAIT1(); }
        __syncthreads();
        const uint32_t stg = (uint32_t)(kc & 1) * STAGE_BYTES;
#pragma unroll
        for (int ks = 0; ks < 4; ks++) {
            const uint32_t kb = ks * 32;
            uint32_t a[4][4];
#pragma unroll
            for (int mt = 0; mt < 4; mt++)
                LDMATRIX_X4(a[mt][0], a[mt][1], a[mt][2], a[mt][3],
                            aAddrBase + stg + mt * (16 * SROW) + kb);
#pragma unroll
            for (int nt2 = 0; nt2 < 2; nt2++) {
                uint32_t b0, b1, b2, b3;
                LDMATRIX_X4(b0, b1, b2, b3, bAddrBase + stg + nt2 * (16 * SROW) + kb);
#pragma unroll
                for (int mt = 0; mt < 4; mt++) {
                    MMA16816(c[mt][nt2 * 2 + 0], a[mt], b0, b1);
                    MMA16816(c[mt][nt2 * 2 + 1], a[mt], b2, b3);
                }
            }
        }
        __syncthreads();
        if (kc + 2 < NC) {
#pragma unroll
            for (int i = 0; i < 8; i++)
                CP_ASYNC16(sdst[i] + stg, gsrc[i] + (kc + 2) * BK);
            CP_COMMIT();
        }
    }

    const int er = lid >> 2;
    const int ec = (lid & 3) * 2;
#pragma unroll
    for (int mt = 0; mt < 4; mt++) {
#pragma unroll
        for (int nt = 0; nt < 4; nt++) {
#pragma unroll
            for (int half = 0; half < 2; half++) {
                int m = bm + wm + mt * 16 + er + half * 8;
                int n = bn + wn + nt * 8 + ec;
                if (m < M && n < Nn) {
                    float v0 = c[mt][nt][half * 2 + 0];
                    float v1 = c[mt][nt][half * 2 + 1];
                    if (bias) { v0 += bias[n]; v1 += bias[n + 1]; }
                    *(float2*)&C[(size_t)m * Nn + n] = make_float2(v0, v1);
                }
            }
        }
    }
}

// ------ fp32 sym Drec (R8-proven math, bit-identical) + COMPARE vs HMMA dots ------
__global__ __launch_bounds__(256) void sgemm_drec_sym_cmp_kernel(const float* __restrict__ A)
{
    const int bi = blockIdx.y, bj = blockIdx.x;
    if (bj < bi) return;
    __shared__ float As[16][64];
    __shared__ float Bs[16][64];
    __shared__ int sg[8], sm[8], smn[8];
    int tid = threadIdx.x;
    int bm = bi * 64, bn = bj * 64;
    int row = tid >> 2;
    int c4  = (tid & 3) * 4;
    int tx = tid & 15, ty = tid >> 4;
    float acc[4][4] = {};
    int am = bm + row, bnr = bn + row;
    for (int k0 = 0; k0 < DIM; k0 += 16) {
        float4 av = make_float4(0.f, 0.f, 0.f, 0.f);
        float4 bv = make_float4(0.f, 0.f, 0.f, 0.f);
        if (am  < NPTS) av = *(const float4*)(A + (size_t)am  * DIM + k0 + c4);
        if (bnr < NPTS) bv = *(const float4*)(A + (size_t)bnr * DIM + k0 + c4);
        As[c4 + 0][row] = av.x; As[c4 + 1][row] = av.y; As[c4 + 2][row] = av.z; As[c4 + 3][row] = av.w;
        Bs[c4 + 0][row] = bv.x; Bs[c4 + 1][row] = bv.y; Bs[c4 + 2][row] = bv.z; Bs[c4 + 3][row] = bv.w;
        __syncthreads();
#pragma unroll
        for (int kk = 0; kk < 16; kk++) {
            float4 a = *(const float4*)&As[kk][ty * 4];
            float4 b = *(const float4*)&Bs[kk][tx * 4];
            acc[0][0] = fmaf(a.x, b.x, acc[0][0]); acc[0][1] = fmaf(a.x, b.y, acc[0][1]);
            acc[0][2] = fmaf(a.x, b.z, acc[0][2]); acc[0][3] = fmaf(a.x, b.w, acc[0][3]);
            acc[1][0] = fmaf(a.y, b.x, acc[1][0]); acc[1][1] = fmaf(a.y, b.y, acc[1][1]);
            acc[1][2] = fmaf(a.y, b.z, acc[1][2]); acc[1][3] = fmaf(a.y, b.w, acc[1][3]);
            acc[2][0] = fmaf(a.z, b.x, acc[2][0]); acc[2][1] = fmaf(a.z, b.y, acc[2][1]);
            acc[2][2] = fmaf(a.z, b.z, acc[2][2]); acc[2][3] = fmaf(a.z, b.w, acc[2][3]);
            acc[3][0] = fmaf(a.w, b.x, acc[3][0]); acc[3][1] = fmaf(a.w, b.y, acc[3][1]);
            acc[3][2] = fmaf(a.w, b.z, acc[3][2]); acc[3][3] = fmaf(a.w, b.w, acc[3][3]);
        }
        __syncthreads();
    }
    int lg = 0, lmod = 0, firstm = 0x7fffffff;
#pragma unroll
    for (int i = 0; i < 4; i++) {
#pragma unroll
        for (int j = 0; j < 4; j++) {
            int m = bm + ty * 4 + i, n = bn + tx * 4 + j;
            if (m < NPTS && n < NPTS) {
                float dhm = g_Drec[(size_t)m * NPTS + n];   // HMMA dot (upper tiles)
                float diff = fabsf(acc[i][j] - dhm);
                if (diff > 0.5f)       { lg++; if (m < firstm) firstm = m; }
                else if (diff > 0.01f) lmod++;
                float sq = fmaxf(g_norms[m] + g_norms[n] - 2.f * acc[i][j], 0.f);
                float v = (m == n) ? CUDART_INF_F : (1.0f / sqrtf(sq));
                g_Drec[(size_t)m * NPTS + n] = v;
                if (bi != bj) g_Drec[(size_t)n * NPTS + m] = v;
            }
        }
    }
    // block reduce counters
    for (int o = 16; o > 0; o >>= 1) {
        lg   += __shfl_down_sync(0xffffffffu, lg, o);
        lmod += __shfl_down_sync(0xffffffffu, lmod, o);
        int om = __shfl_down_sync(0xffffffffu, firstm, o);
        if (om < firstm) firstm = om;
    }
    if ((tid & 31) == 0) { sg[tid >> 5] = lg; sm[tid >> 5] = lmod; smn[tid >> 5] = firstm; }
    __syncthreads();
    if (tid == 0) {
        int tg = 0, tm = 0, tmn = 0x7fffffff;
        for (int i = 0; i < 8; i++) {
            tg += sg[i]; tm += sm[i];
            if (smn[i] < tmn) tmn = smn[i];
        }
        if (tg > 0) { atomicAdd(&g_cnt[0], tg); atomicMin(&g_cnt[2], tmn); }
        if (tm > 0) atomicAdd(&g_cnt[1], tm);
    }
}

// ---------------- sequential greedy FPS (single CTA, ds in registers) ----------------
__global__ __launch_bounds__(1024) void fps_kernel()
{
    int tid = threadIdx.x;
    float ds[6];
#pragma unroll
    for (int i = 0; i < 6; i++) {
        int j = tid + i * 1024;
        ds[i] = (j < NPTS) ? g_Drec[j] : CUDART_INF_F;
    }
    if (tid == 0) g_idx[0] = 0;
    __shared__ float swv[32];
    __shared__ int   swi[32];
    __shared__ int   sbest;
    for (int it = 1; it < KSEL; it++) {
        float bv = ds[0];
        int   bi = tid;
#pragma unroll
        for (int i = 1; i < 6; i++) {
            int j = tid + i * 1024;
            if (j < NPTS && ds[i] < bv) { bv = ds[i]; bi = j; }
        }
#pragma unroll
        for (int o = 16; o > 0; o >>= 1) {
            float ov = __shfl_down_sync(0xffffffffu, bv, o);
            int   oi = __shfl_down_sync(0xffffffffu, bi, o);
            if (ov < bv || (ov == bv && oi < bi)) { bv = ov; bi = oi; }
        }
        int lane = tid & 31, wid = tid >> 5;
        if (lane == 0) { swv[wid] = bv; swi[wid] = bi; }
        __syncthreads();
        if (wid == 0) {
            bv = swv[lane]; bi = swi[lane];
#pragma unroll
            for (int o = 16; o > 0; o >>= 1) {
                float ov = __shfl_down_sync(0xffffffffu, bv, o);
                int   oi = __shfl_down_sync(0xffffffffu, bi, o);
                if (ov < bv || (ov == bv && oi < bi)) { bv = ov; bi = oi; }
            }
            if (lane == 0) { sbest = bi; g_idx[it] = bi; }
        }
        __syncthreads();
        const float* rowp = g_Drec + (size_t)sbest * NPTS;
#pragma unroll
        for (int i = 0; i < 6; i++) {
            int j = tid + i * 1024;
            if (j < NPTS) ds[i] += rowp[j];
        }
    }
}

// ---------------- aff[k,g,n] = (q_kg · kk_ng) / 8 ----------------
__global__ __launch_bounds__(256) void aff_kernel(const float* __restrict__ q,
                                                  const float* __restrict__ kk,
                                                  float* __restrict__ W)
{
    int g  = blockIdx.z;
    int k0 = blockIdx.y * 32;
    int n0 = blockIdx.x * 128;
    __shared__ float Qs[DG][32];
    __shared__ float Ks[DG][128];
    int tid = threadIdx.x;
#pragma unroll
    for (int it = 0; it < 2; it++) {
        int idx = tid + it * 256;
        int r = idx >> 4, c4 = (idx & 15) * 4;
        float4 v = make_float4(0.f, 0.f, 0.f, 0.f);
        if (k0 + r < KSEL) v = *(const float4*)(q + (size_t)(k0 + r) * DIM + g * DG + c4);
        Qs[c4 + 0][r] = v.x; Qs[c4 + 1][r] = v.y; Qs[c4 + 2][r] = v.z; Qs[c4 + 3][r] = v.w;
    }
#pragma unroll
    for (int it = 0; it < 8; it++) {
        int idx = tid + it * 256;
        int r = idx >> 4, c4 = (idx & 15) * 4;
        float4 v = make_float4(0.f, 0.f, 0.f, 0.f);
        if (n0 + r < NPTS) v = *(const float4*)(kk + (size_t)(n0 + r) * DIM + g * DG + c4);
        Ks[c4 + 0][r] = v.x; Ks[c4 + 1][r] = v.y; Ks[c4 + 2][r] = v.z; Ks[c4 + 3][r] = v.w;
    }
    __syncthreads();
    int tx = tid & 31;
    int ty = tid >> 5;
    float acc[4][4] = {};
#pragma unroll 16
    for (int d = 0; d < DG; d++) {
        float4 a = *(const float4*)&Qs[d][ty * 4];
        float4 b = *(const float4*)&Ks[d][tx * 4];
        acc[0][0] = fmaf(a.x, b.x, acc[0][0]); acc[0][1] = fmaf(a.x, b.y, acc[0][1]);
        acc[0][2] = fmaf(a.x, b.z, acc[0][2]); acc[0][3] = fmaf(a.x, b.w, acc[0][3]);
        acc[1][0] = fmaf(a.y, b.x, acc[1][0]); acc[1][1] = fmaf(a.y, b.y, acc[1][1]);
        acc[1][2] = fmaf(a.y, b.z, acc[1][2]); acc[1][3] = fmaf(a.y, b.w, acc[1][3]);
        acc[2][0] = fmaf(a.z, b.x, acc[2][0]); acc[2][1] = fmaf(a.z, b.y, acc[2][1]);
        acc[2][2] = fmaf(a.z, b.z, acc[2][2]); acc[2][3] = fmaf(a.z, b.w, acc[2][3]);
        acc[3][0] = fmaf(a.w, b.x, acc[3][0]); acc[3][1] = fmaf(a.w, b.y, acc[3][1]);
        acc[3][2] = fmaf(a.w, b.z, acc[3][2]); acc[3][3] = fmaf(a.w, b.w, acc[3][3]);
    }
#pragma unroll
    for (int i = 0; i < 4; i++) {
#pragma unroll
        for (int j = 0; j < 4; j++) {
            int k = k0 + ty * 4 + i, n = n0 + tx * 4 + j;
            if (k < KSEL && n < NPTS)
                W[((size_t)k * NG + g) * NPTS + n] = acc[i][j] * 0.125f;
        }
    }
}

// ---------------- position embedding + gate ----------------
__global__ __launch_bounds__(256) void logits_kernel(const float* __restrict__ bboxes,
                                                     const float* __restrict__ Wg,
                                                     const float* __restrict__ bg,
                                                     float* __restrict__ W)
{
    int k = blockIdx.y;
    int tid = threadIdx.x;
    int n = blockIdx.x * 256 + tid;
    __shared__ float sWg[NG][64];
    __shared__ float sbg[NG];
    __shared__ float qb[4];
    for (int i = tid; i < NG * 64; i += 256) sWg[i >> 6][i & 63] = Wg[i];
    if (tid < NG) sbg[tid] = bg[tid];
    if (tid == 0) {
        int qi = g_idx[k];
        float x1 = bboxes[qi * 4 + 0], y1 = bboxes[qi * 4 + 1];
        float x2 = bboxes[qi * 4 + 2], y2 = bboxes[qi * 4 + 3];
        qb[0] = x2 - x1 + 1.f; qb[1] = y2 - y1 + 1.f;
        qb[2] = 0.5f * (x1 + x2); qb[3] = 0.5f * (y1 + y2);
    }
    __syncthreads();
    if (n >= NPTS) return;
    float4 bb = *(const float4*)(bboxes + (size_t)n * 4);
    float wr = bb.z - bb.x + 1.f, hr = bb.w - bb.y + 1.f;
    float cxr = 0.5f * (bb.x + bb.z), cyr = 0.5f * (bb.y + bb.w);
    float w = qb[0], h = qb[1], cx = qb[2], cy = qb[3];
    float pos[4];
    pos[0] = logf(fabsf((cx - cxr) / w) + 1e-3f);
    pos[1] = logf(fabsf((cy - cyr) / h) + 1e-3f);
    pos[2] = logf(w / wr);
    pos[3] = logf(h / hr);
    const float dimmat[8] = { 1.0f, 2.3713737057f, 5.6234132519f, 13.3352143216f,
                              31.6227766017f, 74.9894209332f, 177.8279410039f, 421.6965034286f };
    float gw[NG];
#pragma unroll
    for (int g = 0; g < NG; g++) gw[g] = sbg[g];
#pragma unroll
    for (int c = 0; c < 4; c++) {
        float p100 = pos[c] * 100.f;
#pragma unroll
        for (int f = 0; f < 8; f++) {
            float arg = p100 / dimmat[f];
            float s, co;
            sincosf(arg, &s, &co);
#pragma unroll
            for (int g = 0; g < NG; g++) {
                gw[g] = fmaf(sWg[g][c * 16 + f],     s,  gw[g]);
                gw[g] = fmaf(sWg[g][c * 16 + 8 + f], co, gw[g]);
            }
        }
    }
    size_t base = ((size_t)k * NG) * NPTS + n;
#pragma unroll
    for (int g = 0; g < NG; g++) {
        float awt = fmaxf(gw[g], 0.f);
        W[base + (size_t)g * NPTS] += logf(awt + 1e-6f);
    }
}

// ---------------- softmax over n ----------------
__global__ __launch_bounds__(256) void softmax_kernel(float* __restrict__ W)
{
    __shared__ float buf[NPTS];
    __shared__ float sred[9];
    size_t base = (size_t)blockIdx.x * NPTS;
    int tid = threadIdx.x;
    float mx = -CUDART_INF_F;
    for (int i = tid; i < NPTS; i += 256) { float v = W[base + i]; buf[i] = v; mx = fmaxf(mx, v); }
    for (int o = 16; o > 0; o >>= 1) mx = fmaxf(mx, __shfl_down_sync(0xffffffffu, mx, o));
    if ((tid & 31) == 0) sred[tid >> 5] = mx;
    __syncthreads();
    if (tid == 0) { float m = sred[0]; for (int i = 1; i < 8; i++) m = fmaxf(m, sred[i]); sred[8] = m; }
    __syncthreads();
    mx = sred[8];
    float sum = 0.f;
    for (int i = tid; i < NPTS; i += 256) { float e = expf(buf[i] - mx); buf[i] = e; sum += e; }
    for (int o = 16; o > 0; o >>= 1) sum += __shfl_down_sync(0xffffffffu, sum, o);
    __syncthreads();
    if ((tid & 31) == 0) sred[tid >> 5] = sum;
    __syncthreads();
    if (tid == 0) { float t = 0.f; for (int i = 0; i < 8; i++) t += sred[i]; sred[8] = t; }
    __syncthreads();
    float inv = 1.0f / sred[8];
    for (int i = tid; i < NPTS; i += 256) W[base + i] = buf[i] * inv;
}

// ---------------- out[k, g*64+o] = sum_n soft[k,g,n] * V[n,g,o] + bv ----------------
__global__ __launch_bounds__(256) void out_kernel(const float* __restrict__ W,
                                                  const float* __restrict__ V,
                                                  const float* __restrict__ bv,
                                                  float* __restrict__ out)
{
    int g  = blockIdx.y;
    int k0 = blockIdx.x * 16;
    __shared__ float Ss[16][64];
    __shared__ float Vs[64][65];
    int tid = threadIdx.x;
    int o  = tid & 63;
    int ks = tid >> 6;
    float acc[4] = {0.f, 0.f, 0.f, 0.f};
    for (int n0 = 0; n0 < NPTS; n0 += 64) {
#pragma unroll
        for (int it = 0; it < 4; it++) {
            int idx = tid + it * 256;
            int r = idx >> 6, c = idx & 63;
            int kq = k0 + r, nn = n0 + c;
            Ss[r][c] = (kq < KSEL && nn < NPTS) ? W[((size_t)kq * NG + g) * NPTS + nn] : 0.f;
        }
#pragma unroll
        for (int it = 0; it < 16; it++) {
            int idx = tid + it * 256;
            int r = idx >> 6, c = idx & 63;
            int nn = n0 + r;
            Vs[r][c] = (nn < NPTS) ? V[(size_t)nn * DIM + g * DG + c] : 0.f;
        }
        __syncthreads();
#pragma unroll
        for (int n = 0; n < 64; n++) {
            float v = Vs[n][o];
#pragma unroll
            for (int i = 0; i < 4; i++) acc[i] = fmaf(Ss[ks * 4 + i][n], v, acc[i]);
        }
        __syncthreads();
    }
#pragma unroll
    for (int i = 0; i < 4; i++) {
        int kq = k0 + ks * 4 + i;
        if (kq < KSEL) out[(size_t)kq * DIM + g * DG + o] = acc[i] + bv[g * DG + o];
    }
}

// ---------------- launch ----------------
extern "C" void kernel_launch(void* const* d_in, const int* in_sizes, int n_in,
                              void* d_out, int out_size)
{
    (void)in_sizes; (void)n_in; (void)out_size;
    const float* merged = (const float*)d_in[0];
    const float* bboxes = (const float*)d_in[1];
    const float* Wq     = (const float*)d_in[2];
    const float* bq     = (const float*)d_in[3];
    const float* Wk     = (const float*)d_in[4];
    const float* bk     = (const float*)d_in[5];
    const float* Wg     = (const float*)d_in[6];
    const float* bg     = (const float*)d_in[7];
    const float* Wv     = (const float*)d_in[8];
    const float* bv     = (const float*)d_in[9];
    float* out = (float*)d_out;

    float *p_q, *p_kk, *p_V, *p_W, *p_Drec;
    int* p_idx;
    __half *p_Xa, *p_Xb, *p_Wqs, *p_Wks, *p_Wvs;
    cudaGetSymbolAddress((void**)&p_q,    g_q);
    cudaGetSymbolAddress((void**)&p_kk,   g_kk);
    cudaGetSymbolAddress((void**)&p_V,    g_V);
    cudaGetSymbolAddress((void**)&p_W,    g_W);
    cudaGetSymbolAddress((void**)&p_Drec, g_Drec);
    cudaGetSymbolAddress((void**)&p_idx,  g_idx);
    cudaGetSymbolAddress((void**)&p_Xa,   g_Xa);
    cudaGetSymbolAddress((void**)&p_Xb,   g_Xb);
    cudaGetSymbolAddress((void**)&p_Wqs,  g_Wqs);
    cudaGetSymbolAddress((void**)&p_Wks,  g_Wks);
    cudaGetSymbolAddress((void**)&p_Wvs,  g_Wvs);

    cudaFuncSetAttribute(mma_gemm_kernel, cudaFuncAttributeMaxDynamicSharedMemorySize, GSMEM);

    // 0) reset diag counters; fp16 3-term splits
    zero_cnt_kernel<<<1, 32>>>();
    split3_kernel<<<(NPTS * DIM + 255) / 256, 256>>>(merged, p_Xa, p_Xb, NPTS);
    split3_kernel<<<(DIM * DIM + 255) / 256, 256>>>(Wq, nullptr, p_Wqs, DIM);
    split3_kernel<<<(DIM * DIM + 255) / 256, 256>>>(Wk, nullptr, p_Wks, DIM);
    split3_kernel<<<(DIM * DIM + 255) / 256, 256>>>(Wv, nullptr, p_Wvs, DIM);

    // 1) norms; HMMA dots into g_Drec (upper 128-tiles); fp32 recompute+compare+final epilogue
    norms_kernel<<<NPTS, 256>>>(merged);
    mma_gemm_kernel<<<dim3(47, 47), 256, GSMEM>>>(p_Xa, p_Xb, p_Drec, NPTS, NPTS,
                                                  nullptr, nullptr, 1);
    sgemm_drec_sym_cmp_kernel<<<dim3(94, 94), 256>>>(merged);
    probe_kernel<<<1, 1>>>();

    // 2) sequential greedy FPS (on fp32-exact Drec; bit-identical to R8)
    fps_kernel<<<1, 1024>>>();

    // 3) projections via proven HMMA (q gathered, kk, V)
    mma_gemm_kernel<<<dim3(8, 3),  256, GSMEM>>>(p_Xa, p_Wqs, p_q,  KSEL, DIM, bq, p_idx, 0);
    mma_gemm_kernel<<<dim3(8, 47), 256, GSMEM>>>(p_Xa, p_Wks, p_kk, NPTS, DIM, bk, nullptr, 0);
    mma_gemm_kernel<<<dim3(8, 47), 256, GSMEM>>>(p_Xa, p_Wvs, p_V,  NPTS, DIM, nullptr, nullptr, 0);

    // 4) attention: logits, softmax, weighted sum
    aff_kernel<<<dim3(47, 10, NG), 256>>>(p_q, p_kk, p_W);
    logits_kernel<<<dim3(24, KSEL), 256>>>(bboxes, Wg, bg, p_W);
    softmax_kernel<<<KSEL * NG, 256>>>(p_W);
    out_kernel<<<dim3(19, NG), 256>>>(p_W, p_V, bv, out);
}

// round 11
// speedup vs baseline: 1.4372x; 1.4372x over previous
#include <cuda_runtime.h>
#include <cuda_fp16.h>
#include <math.h>
#include <math_constants.h>
#include <stdint.h>

#define NPTS 6000
#define DIM  1024
#define K3   3072
#define NG   16
#define DG   64
#define KSEL 300

// ---------------- scratch (device globals; no allocation allowed) ----------------
static __device__ float g_norms[NPTS];
static __device__ float g_Drec[(size_t)NPTS * NPTS];          // 144 MB
static __device__ int   g_idx[KSEL];
static __device__ float g_q[KSEL * DIM];
static __device__ float g_kk[(size_t)NPTS * DIM];
static __device__ float g_V[(size_t)NPTS * DIM];
static __device__ float g_W[(size_t)KSEL * NG * NPTS];        // 115 MB logits/soft
static __device__ __half g_Xa[(size_t)NPTS * K3];             // [h | l | h]
static __device__ __half g_Wqs[(size_t)DIM * K3];             // [h | h | l]
static __device__ __half g_Wks[(size_t)DIM * K3];
static __device__ __half g_Wvs[(size_t)DIM * K3];

__device__ __forceinline__ uint32_t smem_u32(const void* p) {
    uint32_t a;
    asm("{ .reg .u64 t; cvta.to.shared.u64 t, %1; cvt.u32.u64 %0, t; }" : "=r"(a) : "l"(p));
    return a;
}
#define CP_ASYNC16(dst, src) \
    asm volatile("cp.async.cg.shared.global [%0], [%1], 16;" :: "r"(dst), "l"(src))
#define CP_COMMIT() asm volatile("cp.async.commit_group;")
#define CP_WAIT1()  asm volatile("cp.async.wait_group 1;")
#define CP_WAIT0()  asm volatile("cp.async.wait_group 0;")
#define LDMATRIX_X4(r0, r1, r2, r3, a) \
    asm volatile("ldmatrix.sync.aligned.m8n8.x4.shared.b16 {%0,%1,%2,%3}, [%4];" \
        : "=r"(r0), "=r"(r1), "=r"(r2), "=r"(r3) : "r"(a))
#define MMA16816(c, a, b0, b1) \
    asm volatile("mma.sync.aligned.m16n8k16.row.col.f32.f16.f16.f32 " \
        "{%0,%1,%2,%3}, {%4,%5,%6,%7}, {%8,%9}, {%0,%1,%2,%3};" \
        : "+f"((c)[0]), "+f"((c)[1]), "+f"((c)[2]), "+f"((c)[3]) \
        : "r"((a)[0]), "r"((a)[1]), "r"((a)[2]), "r"((a)[3]), "r"(b0), "r"(b1))
#define FMA2(acc, a, b) \
    asm("fma.rn.f32x2 %0, %1, %2, %0;" : "+l"(acc) : "l"(a), "l"(b))

// ---------------- 3-term fp16 split --------------------------------------------
__global__ __launch_bounds__(256) void split3_kernel(const float* __restrict__ X,
                                                     __half* __restrict__ Xa,
                                                     __half* __restrict__ Xb,
                                                     int rows) {
    size_t i = (size_t)blockIdx.x * 256 + threadIdx.x;
    if (i >= (size_t)rows * DIM) return;
    size_t r = i / DIM, c = i % DIM;
    float x = X[i];
    __half h = __float2half(x);
    __half l = __float2half(x - __half2float(h));
    if (Xa) {
        Xa[r * K3 + c]            = h;
        Xa[r * K3 + DIM + c]      = l;
        Xa[r * K3 + 2 * DIM + c]  = h;
    }
    if (Xb) {
        Xb[r * K3 + c]            = h;
        Xb[r * K3 + DIM + c]      = h;
        Xb[r * K3 + 2 * DIM + c]  = l;
    }
}

// ---------------- row squared-norms ----------------
__global__ __launch_bounds__(256) void norms_kernel(const float* __restrict__ X) {
    int r = blockIdx.x;
    const float* x = X + (size_t)r * DIM;
    float s = 0.f;
    for (int c = threadIdx.x; c < DIM; c += 256) { float v = x[c]; s = fmaf(v, v, s); }
    __shared__ float sred[8];
    for (int o = 16; o > 0; o >>= 1) s += __shfl_down_sync(0xffffffffu, s, o);
    if ((threadIdx.x & 31) == 0) sred[threadIdx.x >> 5] = s;
    __syncthreads();
    if (threadIdx.x == 0) {
        float t = 0.f;
        for (int i = 0; i < 8; i++) t += sred[i];
        g_norms[r] = t;
    }
}

// ====== fp32x2 (FFMA2) symmetric Drec: tile 64(m) x 128(n), upper + mirror ======
// Per-lane IEEE fp32 FMA, identical k-order as the R8 kernel => bit-identical Drec.
#define ASTRIDE 512              // bytes per k-row of As2 (64 dup-pairs)
#define BSTRIDE 768              // bytes per k-row of Bs2 (16 groups x 6 pairs)
__global__ __launch_bounds__(256) void drec_f32x2_kernel(const float* __restrict__ A)
{
    const int bj = blockIdx.x, bi = blockIdx.y;      // n-tile (128), m-tile (64)
    if (128 * bj + 127 < 64 * bi) return;            // tile fully below diagonal
    const int bm = bi * 64, bn = bj * 128;
    __shared__ char As2[16 * ASTRIDE];               // dup pairs {a,a}
    __shared__ char Bs2[16 * BSTRIDE];               // pairs {b_even,b_odd}, 6-pair groups
    const int tid = threadIdx.x;
    const int tx = tid & 15;                         // n-group (8 cols)
    const int ty = tid >> 4;                         // m-group (4 rows)

    uint64_t acc2[4][4];
#pragma unroll
    for (int i = 0; i < 4; i++)
#pragma unroll
        for (int j = 0; j < 4; j++) acc2[i][j] = 0ull;

    // loader assignments
    const int a_mr = tid & 63, a_kq = (tid >> 6) * 4;
    const int a_row = (bm + a_mr < NPTS) ? (bm + a_mr) : (NPTS - 1);
    const uint32_t aBase = smem_u32(As2);
    const uint32_t bBase = smem_u32(Bs2);

    for (int k0 = 0; k0 < DIM; k0 += 16) {
        // A: 64 rows x 16 k
        {
            float4 v = *(const float4*)(A + (size_t)a_row * DIM + k0 + a_kq);
            uint32_t ad = aBase + (uint32_t)(a_kq * ASTRIDE + a_mr * 8);
            const float av[4] = {v.x, v.y, v.z, v.w};
#pragma unroll
            for (int s = 0; s < 4; s++) {
                uint64_t dup = (((uint64_t)__float_as_uint(av[s])) << 32) | __float_as_uint(av[s]);
                asm volatile("st.shared.b64 [%0], %1;" :: "r"(ad + s * ASTRIDE), "l"(dup));
            }
        }
        // B: 128 rows x 16 k (two passes)
#pragma unroll
        for (int it = 0; it < 2; it++) {
            int u = tid + it * 256;
            int n_r = u & 127;
            int kq = (u >> 7) * 4;
            int row = (bn + n_r < NPTS) ? (bn + n_r) : (NPTS - 1);
            float4 v = *(const float4*)(A + (size_t)row * DIM + k0 + kq);
            int t = n_r >> 3, j = (n_r >> 1) & 3, h = n_r & 1;
            uint32_t bd = bBase + (uint32_t)(kq * BSTRIDE + t * 48 + j * 8 + h * 4);
            const float bv[4] = {v.x, v.y, v.z, v.w};
#pragma unroll
            for (int s = 0; s < 4; s++)
                asm volatile("st.shared.b32 [%0], %1;" :: "r"(bd + s * BSTRIDE), "r"(__float_as_uint(bv[s])));
        }
        __syncthreads();
        const uint32_t aOff = aBase + (uint32_t)(ty * 32);
        const uint32_t bOff = bBase + (uint32_t)(tx * 48);
#pragma unroll
        for (int kk = 0; kk < 16; kk++) {
            uint64_t pa[4], pb[4];
#pragma unroll
            for (int i = 0; i < 4; i++)
                asm volatile("ld.shared.b64 %0, [%1];" : "=l"(pa[i]) : "r"(aOff + kk * ASTRIDE + i * 8));
#pragma unroll
            for (int j = 0; j < 4; j++)
                asm volatile("ld.shared.b64 %0, [%1];" : "=l"(pb[j]) : "r"(bOff + kk * BSTRIDE + j * 8));
#pragma unroll
            for (int i = 0; i < 4; i++)
#pragma unroll
                for (int j = 0; j < 4; j++)
                    FMA2(acc2[i][j], pa[i], pb[j]);
        }
        __syncthreads();
    }

    // epilogue: v = 1/sqrt(max(nm+nn-2dot,0)), diag inf; write upper + mirror
#pragma unroll
    for (int i = 0; i < 4; i++) {
        int m = bm + ty * 4 + i;
        if (m >= NPTS) continue;
        float nm = g_norms[m];
#pragma unroll
        for (int j = 0; j < 4; j++) {
#pragma unroll
            for (int h = 0; h < 2; h++) {
                int n = bn + tx * 8 + 2 * j + h;
                if (n < NPTS && n >= m) {
                    uint32_t bits = (h == 0) ? (uint32_t)acc2[i][j] : (uint32_t)(acc2[i][j] >> 32);
                    float dot = __uint_as_float(bits);
                    float sq = fmaxf(nm + g_norms[n] - 2.f * dot, 0.f);
                    float v = (m == n) ? CUDART_INF_F : (1.0f / sqrtf(sq));
                    g_Drec[(size_t)m * NPTS + n] = v;
                    if (n > m) g_Drec[(size_t)n * NPTS + m] = v;
                }
            }
        }
    }
}

// =============== fp16 HMMA GEMM (R8-proven, projections only) ===============
#define BK 64
#define NC (K3 / BK)
#define SROW 144
#define STAGE_BYTES (2 * 128 * SROW)
#define GSMEM (2 * STAGE_BYTES)

__global__ __launch_bounds__(256) void mma_gemm_kernel(
    const __half* __restrict__ A, const __half* __restrict__ B,
    float* __restrict__ C, int M, int Nn,
    const float* __restrict__ bias, const int* __restrict__ rowIdx)
{
    extern __shared__ char smem[];
    const uint32_t sb = smem_u32(smem);
    const int tid = threadIdx.x;
    const int wid = tid >> 5;
    const int lid = tid & 31;
    const int bm = blockIdx.y * 128;
    const int bn = blockIdx.x * 128;

    const __half* gsrc[8];
    uint32_t sdst[8];
#pragma unroll
    for (int i = 0; i < 8; i++) {
        int u = tid + i * 256;
        int mat = u >> 10;
        int r = (u >> 3) & 127;
        int q = u & 7;
        int grow;
        if (mat == 0) {
            grow = bm + r; if (grow > M - 1) grow = M - 1;
            if (rowIdx) grow = rowIdx[grow];
            gsrc[i] = A + (size_t)grow * K3 + q * 8;
        } else {
            grow = bn + r; if (grow > Nn - 1) grow = Nn - 1;
            gsrc[i] = B + (size_t)grow * K3 + q * 8;
        }
        sdst[i] = sb + (uint32_t)(mat * 128 * SROW + r * SROW + q * 16);
    }

#pragma unroll
    for (int i = 0; i < 8; i++) CP_ASYNC16(sdst[i], gsrc[i]);
    CP_COMMIT();
#pragma unroll
    for (int i = 0; i < 8; i++) CP_ASYNC16(sdst[i] + STAGE_BYTES, gsrc[i] + BK);
    CP_COMMIT();

    const int wm = (wid >> 2) * 64;
    const int wn = (wid & 3) * 32;
    float c[4][4][4] = {};

    const uint32_t aAddrBase = sb + (uint32_t)((wm + (lid & 15)) * SROW + (lid >> 4) * 16);
    const uint32_t bAddrBase = sb + (uint32_t)(128 * SROW + (wn + (lid >> 4) * 8 + (lid & 7)) * SROW + ((lid >> 3) & 1) * 16);

    for (int kc = 0; kc < NC; kc++) {
        if (kc == NC - 1) { CP_WAIT0(); } else { CP_WAIT1(); }
        __syncthreads();
        const uint32_t stg = (uint32_t)(kc & 1) * STAGE_BYTES;
#pragma unroll
        for (int ks = 0; ks < 4; ks++) {
            const uint32_t kb = ks * 32;
            uint32_t a[4][4];
#pragma unroll
            for (int mt = 0; mt < 4; mt++)
                LDMATRIX_X4(a[mt][0], a[mt][1], a[mt][2], a[mt][3],
                            aAddrBase + stg + mt * (16 * SROW) + kb);
#pragma unroll
            for (int nt2 = 0; nt2 < 2; nt2++) {
                uint32_t b0, b1, b2, b3;
                LDMATRIX_X4(b0, b1, b2, b3, bAddrBase + stg + nt2 * (16 * SROW) + kb);
#pragma unroll
                for (int mt = 0; mt < 4; mt++) {
                    MMA16816(c[mt][nt2 * 2 + 0], a[mt], b0, b1);
                    MMA16816(c[mt][nt2 * 2 + 1], a[mt], b2, b3);
                }
            }
        }
        __syncthreads();
        if (kc + 2 < NC) {
#pragma unroll
            for (int i = 0; i < 8; i++)
                CP_ASYNC16(sdst[i] + stg, gsrc[i] + (kc + 2) * BK);
            CP_COMMIT();
        }
    }

    const int er = lid >> 2;
    const int ec = (lid & 3) * 2;
#pragma unroll
    for (int mt = 0; mt < 4; mt++) {
#pragma unroll
        for (int nt = 0; nt < 4; nt++) {
#pragma unroll
            for (int half = 0; half < 2; half++) {
                int m = bm + wm + mt * 16 + er + half * 8;
                int n = bn + wn + nt * 8 + ec;
                if (m < M && n < Nn) {
                    float v0 = c[mt][nt][half * 2 + 0];
                    float v1 = c[mt][nt][half * 2 + 1];
                    if (bias) { v0 += bias[n]; v1 += bias[n + 1]; }
                    *(float2*)&C[(size_t)m * Nn + n] = make_float2(v0, v1);
                }
            }
        }
    }
}

// ---------------- sequential greedy FPS (single CTA, ds in registers) ----------------
__global__ __launch_bounds__(1024) void fps_kernel()
{
    int tid = threadIdx.x;
    float ds[6];
#pragma unroll
    for (int i = 0; i < 6; i++) {
        int j = tid + i * 1024;
        ds[i] = (j < NPTS) ? g_Drec[j] : CUDART_INF_F;
    }
    if (tid == 0) g_idx[0] = 0;
    __shared__ float swv[32];
    __shared__ int   swi[32];
    __shared__ int   sbest;
    for (int it = 1; it < KSEL; it++) {
        float bv = ds[0];
        int   bi = tid;
#pragma unroll
        for (int i = 1; i < 6; i++) {
            int j = tid + i * 1024;
            if (j < NPTS && ds[i] < bv) { bv = ds[i]; bi = j; }
        }
#pragma unroll
        for (int o = 16; o > 0; o >>= 1) {
            float ov = __shfl_down_sync(0xffffffffu, bv, o);
            int   oi = __shfl_down_sync(0xffffffffu, bi, o);
            if (ov < bv || (ov == bv && oi < bi)) { bv = ov; bi = oi; }
        }
        int lane = tid & 31, wid = tid >> 5;
        if (lane == 0) { swv[wid] = bv; swi[wid] = bi; }
        __syncthreads();
        if (wid == 0) {
            bv = swv[lane]; bi = swi[lane];
#pragma unroll
            for (int o = 16; o > 0; o >>= 1) {
                float ov = __shfl_down_sync(0xffffffffu, bv, o);
                int   oi = __shfl_down_sync(0xffffffffu, bi, o);
                if (ov < bv || (ov == bv && oi < bi)) { bv = ov; bi = oi; }
            }
            if (lane == 0) { sbest = bi; g_idx[it] = bi; }
        }
        __syncthreads();
        const float* rowp = g_Drec + (size_t)sbest * NPTS;
#pragma unroll
        for (int i = 0; i < 6; i++) {
            int j = tid + i * 1024;
            if (j < NPTS) ds[i] += rowp[j];
        }
    }
}

// ---------------- aff[k,g,n] = (q_kg · kk_ng) / 8 ----------------
__global__ __launch_bounds__(256) void aff_kernel(const float* __restrict__ q,
                                                  const float* __restrict__ kk,
                                                  float* __restrict__ W)
{
    int g  = blockIdx.z;
    int k0 = blockIdx.y * 32;
    int n0 = blockIdx.x * 128;
    __shared__ float Qs[DG][32];
    __shared__ float Ks[DG][128];
    int tid = threadIdx.x;
#pragma unroll
    for (int it = 0; it < 2; it++) {
        int idx = tid + it * 256;
        int r = idx >> 4, c4 = (idx & 15) * 4;
        float4 v = make_float4(0.f, 0.f, 0.f, 0.f);
        if (k0 + r < KSEL) v = *(const float4*)(q + (size_t)(k0 + r) * DIM + g * DG + c4);
        Qs[c4 + 0][r] = v.x; Qs[c4 + 1][r] = v.y; Qs[c4 + 2][r] = v.z; Qs[c4 + 3][r] = v.w;
    }
#pragma unroll
    for (int it = 0; it < 8; it++) {
        int idx = tid + it * 256;
        int r = idx >> 4, c4 = (idx & 15) * 4;
        float4 v = make_float4(0.f, 0.f, 0.f, 0.f);
        if (n0 + r < NPTS) v = *(const float4*)(kk + (size_t)(n0 + r) * DIM + g * DG + c4);
        Ks[c4 + 0][r] = v.x; Ks[c4 + 1][r] = v.y; Ks[c4 + 2][r] = v.z; Ks[c4 + 3][r] = v.w;
    }
    __syncthreads();
    int tx = tid & 31;
    int ty = tid >> 5;
    float acc[4][4] = {};
#pragma unroll 16
    for (int d = 0; d < DG; d++) {
        float4 a = *(const float4*)&Qs[d][ty * 4];
        float4 b = *(const float4*)&Ks[d][tx * 4];
        acc[0][0] = fmaf(a.x, b.x, acc[0][0]); acc[0][1] = fmaf(a.x, b.y, acc[0][1]);
        acc[0][2] = fmaf(a.x, b.z, acc[0][2]); acc[0][3] = fmaf(a.x, b.w, acc[0][3]);
        acc[1][0] = fmaf(a.y, b.x, acc[1][0]); acc[1][1] = fmaf(a.y, b.y, acc[1][1]);
        acc[1][2] = fmaf(a.y, b.z, acc[1][2]); acc[1][3] = fmaf(a.y, b.w, acc[1][3]);
        acc[2][0] = fmaf(a.z, b.x, acc[2][0]); acc[2][1] = fmaf(a.z, b.y, acc[2][1]);
        acc[2][2] = fmaf(a.z, b.z, acc[2][2]); acc[2][3] = fmaf(a.z, b.w, acc[2][3]);
        acc[3][0] = fmaf(a.w, b.x, acc[3][0]); acc[3][1] = fmaf(a.w, b.y, acc[3][1]);
        acc[3][2] = fmaf(a.w, b.z, acc[3][2]); acc[3][3] = fmaf(a.w, b.w, acc[3][3]);
    }
#pragma unroll
    for (int i = 0; i < 4; i++) {
#pragma unroll
        for (int j = 0; j < 4; j++) {
            int k = k0 + ty * 4 + i, n = n0 + tx * 4 + j;
            if (k < KSEL && n < NPTS)
                W[((size_t)k * NG + g) * NPTS + n] = acc[i][j] * 0.125f;
        }
    }
}

// ---------------- position embedding + gate ----------------
__global__ __launch_bounds__(256) void logits_kernel(const float* __restrict__ bboxes,
                                                     const float* __restrict__ Wg,
                                                     const float* __restrict__ bg,
                                                     float* __restrict__ W)
{
    int k = blockIdx.y;
    int tid = threadIdx.x;
    int n = blockIdx.x * 256 + tid;
    __shared__ float sWg[NG][64];
    __shared__ float sbg[NG];
    __shared__ float qb[4];
    for (int i = tid; i < NG * 64; i += 256) sWg[i >> 6][i & 63] = Wg[i];
    if (tid < NG) sbg[tid] = bg[tid];
    if (tid == 0) {
        int qi = g_idx[k];
        float x1 = bboxes[qi * 4 + 0], y1 = bboxes[qi * 4 + 1];
        float x2 = bboxes[qi * 4 + 2], y2 = bboxes[qi * 4 + 3];
        qb[0] = x2 - x1 + 1.f; qb[1] = y2 - y1 + 1.f;
        qb[2] = 0.5f * (x1 + x2); qb[3] = 0.5f * (y1 + y2);
    }
    __syncthreads();
    if (n >= NPTS) return;
    float4 bb = *(const float4*)(bboxes + (size_t)n * 4);
    float wr = bb.z - bb.x + 1.f, hr = bb.w - bb.y + 1.f;
    float cxr = 0.5f * (bb.x + bb.z), cyr = 0.5f * (bb.y + bb.w);
    float w = qb[0], h = qb[1], cx = qb[2], cy = qb[3];
    float pos[4];
    pos[0] = logf(fabsf((cx - cxr) / w) + 1e-3f);
    pos[1] = logf(fabsf((cy - cyr) / h) + 1e-3f);
    pos[2] = logf(w / wr);
    pos[3] = logf(h / hr);
    const float dimmat[8] = { 1.0f, 2.3713737057f, 5.6234132519f, 13.3352143216f,
                              31.6227766017f, 74.9894209332f, 177.8279410039f, 421.6965034286f };
    float gw[NG];
#pragma unroll
    for (int g = 0; g < NG; g++) gw[g] = sbg[g];
#pragma unroll
    for (int c = 0; c < 4; c++) {
        float p100 = pos[c] * 100.f;
#pragma unroll
        for (int f = 0; f < 8; f++) {
            float arg = p100 / dimmat[f];
            float s, co;
            sincosf(arg, &s, &co);
#pragma unroll
            for (int g = 0; g < NG; g++) {
                gw[g] = fmaf(sWg[g][c * 16 + f],     s,  gw[g]);
                gw[g] = fmaf(sWg[g][c * 16 + 8 + f], co, gw[g]);
            }
        }
    }
    size_t base = ((size_t)k * NG) * NPTS + n;
#pragma unroll
    for (int g = 0; g < NG; g++) {
        float awt = fmaxf(gw[g], 0.f);
        W[base + (size_t)g * NPTS] += logf(awt + 1e-6f);
    }
}

// ---------------- softmax over n ----------------
__global__ __launch_bounds__(256) void softmax_kernel(float* __restrict__ W)
{
    __shared__ float buf[NPTS];
    __shared__ float sred[9];
    size_t base = (size_t)blockIdx.x * NPTS;
    int tid = threadIdx.x;
    float mx = -CUDART_INF_F;
    for (int i = tid; i < NPTS; i += 256) { float v = W[base + i]; buf[i] = v; mx = fmaxf(mx, v); }
    for (int o = 16; o > 0; o >>= 1) mx = fmaxf(mx, __shfl_down_sync(0xffffffffu, mx, o));
    if ((tid & 31) == 0) sred[tid >> 5] = mx;
    __syncthreads();
    if (tid == 0) { float m = sred[0]; for (int i = 1; i < 8; i++) m = fmaxf(m, sred[i]); sred[8] = m; }
    __syncthreads();
    mx = sred[8];
    float sum = 0.f;
    for (int i = tid; i < NPTS; i += 256) { float e = expf(buf[i] - mx); buf[i] = e; sum += e; }
    for (int o = 16; o > 0; o >>= 1) sum += __shfl_down_sync(0xffffffffu, sum, o);
    __syncthreads();
    if ((tid & 31) == 0) sred[tid >> 5] = sum;
    __syncthreads();
    if (tid == 0) { float t = 0.f; for (int i = 0; i < 8; i++) t += sred[i]; sred[8] = t; }
    __syncthreads();
    float inv = 1.0f / sred[8];
    for (int i = tid; i < NPTS; i += 256) W[base + i] = buf[i] * inv;
}

// ---------------- out[k, g*64+o] = sum_n soft[k,g,n] * V[n,g,o] + bv ----------------
__global__ __launch_bounds__(256) void out_kernel(const float* __restrict__ W,
                                                  const float* __restrict__ V,
                                                  const float* __restrict__ bv,
                                                  float* __restrict__ out)
{
    int g  = blockIdx.y;
    int k0 = blockIdx.x * 16;
    __shared__ float Ss[16][64];
    __shared__ float Vs[64][65];
    int tid = threadIdx.x;
    int o  = tid & 63;
    int ks = tid >> 6;
    float acc[4] = {0.f, 0.f, 0.f, 0.f};
    for (int n0 = 0; n0 < NPTS; n0 += 64) {
#pragma unroll
        for (int it = 0; it < 4; it++) {
            int idx = tid + it * 256;
            int r = idx >> 6, c = idx & 63;
            int kq = k0 + r, nn = n0 + c;
            Ss[r][c] = (kq < KSEL && nn < NPTS) ? W[((size_t)kq * NG + g) * NPTS + nn] : 0.f;
        }
#pragma unroll
        for (int it = 0; it < 16; it++) {
            int idx = tid + it * 256;
            int r = idx >> 6, c = idx & 63;
            int nn = n0 + r;
            Vs[r][c] = (nn < NPTS) ? V[(size_t)nn * DIM + g * DG + c] : 0.f;
        }
        __syncthreads();
#pragma unroll
        for (int n = 0; n < 64; n++) {
            float v = Vs[n][o];
#pragma unroll
            for (int i = 0; i < 4; i++) acc[i] = fmaf(Ss[ks * 4 + i][n], v, acc[i]);
        }
        __syncthreads();
    }
#pragma unroll
    for (int i = 0; i < 4; i++) {
        int kq = k0 + ks * 4 + i;
        if (kq < KSEL) out[(size_t)kq * DIM + g * DG + o] = acc[i] + bv[g * DG + o];
    }
}

// ---------------- launch ----------------
extern "C" void kernel_launch(void* const* d_in, const int* in_sizes, int n_in,
                              void* d_out, int out_size)
{
    (void)in_sizes; (void)n_in; (void)out_size;
    const float* merged = (const float*)d_in[0];
    const float* bboxes = (const float*)d_in[1];
    const float* Wq     = (const float*)d_in[2];
    const float* bq     = (const float*)d_in[3];
    const float* Wk     = (const float*)d_in[4];
    const float* bk     = (const float*)d_in[5];
    const float* Wg     = (const float*)d_in[6];
    const float* bg     = (const float*)d_in[7];
    const float* Wv     = (const float*)d_in[8];
    const float* bv     = (const float*)d_in[9];
    float* out = (float*)d_out;

    float *p_q, *p_kk, *p_V, *p_W;
    int* p_idx;
    __half *p_Xa, *p_Wqs, *p_Wks, *p_Wvs;
    cudaGetSymbolAddress((void**)&p_q,   g_q);
    cudaGetSymbolAddress((void**)&p_kk,  g_kk);
    cudaGetSymbolAddress((void**)&p_V,   g_V);
    cudaGetSymbolAddress((void**)&p_W,   g_W);
    cudaGetSymbolAddress((void**)&p_idx, g_idx);
    cudaGetSymbolAddress((void**)&p_Xa,  g_Xa);
    cudaGetSymbolAddress((void**)&p_Wqs, g_Wqs);
    cudaGetSymbolAddress((void**)&p_Wks, g_Wks);
    cudaGetSymbolAddress((void**)&p_Wvs, g_Wvs);

    cudaFuncSetAttribute(mma_gemm_kernel, cudaFuncAttributeMaxDynamicSharedMemorySize, GSMEM);

    // 0) fp16 3-term splits (X gets A-pattern; weights get B-pattern)
    split3_kernel<<<(NPTS * DIM + 255) / 256, 256>>>(merged, p_Xa, nullptr, NPTS);
    split3_kernel<<<(DIM * DIM + 255) / 256, 256>>>(Wq, nullptr, p_Wqs, DIM);
    split3_kernel<<<(DIM * DIM + 255) / 256, 256>>>(Wk, nullptr, p_Wks, DIM);
    split3_kernel<<<(DIM * DIM + 255) / 256, 256>>>(Wv, nullptr, p_Wvs, DIM);

    // 1) norms + Drec via packed-fp32 FFMA2 symmetric kernel (bit-identical to R8)
    norms_kernel<<<NPTS, 256>>>(merged);
    drec_f32x2_kernel<<<dim3(47, 94), 256>>>(merged);

    // 2) sequential greedy FPS (identical values => identical selection)
    fps_kernel<<<1, 1024>>>();

    // 3) projections via proven HMMA (q gathered, kk, V)
    mma_gemm_kernel<<<dim3(8, 3),  256, GSMEM>>>(p_Xa, p_Wqs, p_q,  KSEL, DIM, bq, p_idx);
    mma_gemm_kernel<<<dim3(8, 47), 256, GSMEM>>>(p_Xa, p_Wks, p_kk, NPTS, DIM, bk, nullptr);
    mma_gemm_kernel<<<dim3(8, 47), 256, GSMEM>>>(p_Xa, p_Wvs, p_V,  NPTS, DIM, nullptr, nullptr);

    // 4) attention: logits, softmax, weighted sum
    aff_kernel<<<dim3(47, 10, NG), 256>>>(p_q, p_kk, p_W);
    logits_kernel<<<dim3(24, KSEL), 256>>>(bboxes, Wg, bg, p_W);
    softmax_kernel<<<KSEL * NG, 256>>>(p_W);
    out_kernel<<<dim3(19, NG), 256>>>(p_W, p_V, bv, out);
}

// round 13
// speedup vs baseline: 1.5352x; 1.0682x over previous
#include <cuda_runtime.h>
#include <cuda_fp16.h>
#include <math.h>
#include <math_constants.h>
#include <stdint.h>

#define NPTS 6000
#define DIM  1024
#define K3   3072
#define NG   16
#define DG   64
#define KSEL 300

// ---------------- scratch (device globals; no allocation allowed) ----------------
static __device__ float g_norms[NPTS];
static __device__ float g_Drec[(size_t)NPTS * NPTS];          // 144 MB
static __device__ int   g_idx[KSEL];
static __device__ float g_q[KSEL * DIM];
static __device__ float g_kk[(size_t)NPTS * DIM];
static __device__ float g_V[(size_t)NPTS * DIM];
static __device__ float g_W[(size_t)KSEL * NG * NPTS];        // 115 MB logits/soft
static __device__ __half g_Xa[(size_t)NPTS * K3];             // [h | l | h]
static __device__ __half g_Wqs[(size_t)DIM * K3];             // [h | h | l]
static __device__ __half g_Wks[(size_t)DIM * K3];
static __device__ __half g_Wvs[(size_t)DIM * K3];

__device__ __forceinline__ uint32_t smem_u32(const void* p) {
    uint32_t a;
    asm("{ .reg .u64 t; cvta.to.shared.u64 t, %1; cvt.u32.u64 %0, t; }" : "=r"(a) : "l"(p));
    return a;
}
#define CP_ASYNC16(dst, src) \
    asm volatile("cp.async.cg.shared.global [%0], [%1], 16;" :: "r"(dst), "l"(src))
#define CP_COMMIT() asm volatile("cp.async.commit_group;")
#define CP_WAIT1()  asm volatile("cp.async.wait_group 1;")
#define CP_WAIT0()  asm volatile("cp.async.wait_group 0;")
#define LDMATRIX_X4(r0, r1, r2, r3, a) \
    asm volatile("ldmatrix.sync.aligned.m8n8.x4.shared.b16 {%0,%1,%2,%3}, [%4];" \
        : "=r"(r0), "=r"(r1), "=r"(r2), "=r"(r3) : "r"(a))
#define MMA16816(c, a, b0, b1) \
    asm volatile("mma.sync.aligned.m16n8k16.row.col.f32.f16.f16.f32 " \
        "{%0,%1,%2,%3}, {%4,%5,%6,%7}, {%8,%9}, {%0,%1,%2,%3};" \
        : "+f"((c)[0]), "+f"((c)[1]), "+f"((c)[2]), "+f"((c)[3]) \
        : "r"((a)[0]), "r"((a)[1]), "r"((a)[2]), "r"((a)[3]), "r"(b0), "r"(b1))

// ---------------- 3-term fp16 split --------------------------------------------
__global__ __launch_bounds__(256) void split3_kernel(const float* __restrict__ X,
                                                     __half* __restrict__ Xa,
                                                     __half* __restrict__ Xb,
                                                     int rows) {
    size_t i = (size_t)blockIdx.x * 256 + threadIdx.x;
    if (i >= (size_t)rows * DIM) return;
    size_t r = i / DIM, c = i % DIM;
    float x = X[i];
    __half h = __float2half(x);
    __half l = __float2half(x - __half2float(h));
    if (Xa) {
        Xa[r * K3 + c]            = h;
        Xa[r * K3 + DIM + c]      = l;
        Xa[r * K3 + 2 * DIM + c]  = h;
    }
    if (Xb) {
        Xb[r * K3 + c]            = h;
        Xb[r * K3 + DIM + c]      = h;
        Xb[r * K3 + 2 * DIM + c]  = l;
    }
}

// ---------------- row squared-norms ----------------
__global__ __launch_bounds__(256) void norms_kernel(const float* __restrict__ X) {
    int r = blockIdx.x;
    const float* x = X + (size_t)r * DIM;
    float s = 0.f;
    for (int c = threadIdx.x; c < DIM; c += 256) { float v = x[c]; s = fmaf(v, v, s); }
    __shared__ float sred[8];
    for (int o = 16; o > 0; o >>= 1) s += __shfl_down_sync(0xffffffffu, s, o);
    if ((threadIdx.x & 31) == 0) sred[threadIdx.x >> 5] = s;
    __syncthreads();
    if (threadIdx.x == 0) {
        float t = 0.f;
        for (int i = 0; i < 8; i++) t += sred[i];
        g_norms[r] = t;
    }
}

// ------ symmetric fp32 Drec GEMM (R8 math, software-pipelined loads) ------
__global__ __launch_bounds__(256) void sgemm_drec_sym_kernel(const float* __restrict__ A)
{
    const int bi = blockIdx.y, bj = blockIdx.x;
    if (bj < bi) return;                      // upper triangle only
    __shared__ float As[16][64];
    __shared__ float Bs[16][64];
    int tid = threadIdx.x;
    int bm = bi * 64, bn = bj * 64;
    int row = tid >> 2;
    int c4  = (tid & 3) * 4;
    int tx = tid & 15, ty = tid >> 4;
    float acc[4][4] = {};
    int am = bm + row, bnr = bn + row;
    const float* ap = (am  < NPTS) ? (A + (size_t)am  * DIM + c4) : nullptr;
    const float* bp = (bnr < NPTS) ? (A + (size_t)bnr * DIM + c4) : nullptr;

    float4 av = ap ? *(const float4*)ap : make_float4(0.f, 0.f, 0.f, 0.f);
    float4 bv = bp ? *(const float4*)bp : make_float4(0.f, 0.f, 0.f, 0.f);

    for (int k0 = 0; k0 < DIM; k0 += 16) {
        As[c4 + 0][row] = av.x; As[c4 + 1][row] = av.y; As[c4 + 2][row] = av.z; As[c4 + 3][row] = av.w;
        Bs[c4 + 0][row] = bv.x; Bs[c4 + 1][row] = bv.y; Bs[c4 + 2][row] = bv.z; Bs[c4 + 3][row] = bv.w;
        __syncthreads();
        // issue next-chunk loads early (overlaps with compute)
        if (k0 + 16 < DIM) {
            if (ap) av = *(const float4*)(ap + k0 + 16);
            if (bp) bv = *(const float4*)(bp + k0 + 16);
        }
#pragma unroll
        for (int kk = 0; kk < 16; kk++) {
            float4 a = *(const float4*)&As[kk][ty * 4];
            float4 b = *(const float4*)&Bs[kk][tx * 4];
            acc[0][0] = fmaf(a.x, b.x, acc[0][0]); acc[0][1] = fmaf(a.x, b.y, acc[0][1]);
            acc[0][2] = fmaf(a.x, b.z, acc[0][2]); acc[0][3] = fmaf(a.x, b.w, acc[0][3]);
            acc[1][0] = fmaf(a.y, b.x, acc[1][0]); acc[1][1] = fmaf(a.y, b.y, acc[1][1]);
            acc[1][2] = fmaf(a.y, b.z, acc[1][2]); acc[1][3] = fmaf(a.y, b.w, acc[1][3]);
            acc[2][0] = fmaf(a.z, b.x, acc[2][0]); acc[2][1] = fmaf(a.z, b.y, acc[2][1]);
            acc[2][2] = fmaf(a.z, b.z, acc[2][2]); acc[2][3] = fmaf(a.z, b.w, acc[2][3]);
            acc[3][0] = fmaf(a.w, b.x, acc[3][0]); acc[3][1] = fmaf(a.w, b.y, acc[3][1]);
            acc[3][2] = fmaf(a.w, b.z, acc[3][2]); acc[3][3] = fmaf(a.w, b.w, acc[3][3]);
        }
        __syncthreads();
    }
#pragma unroll
    for (int i = 0; i < 4; i++) {
#pragma unroll
        for (int j = 0; j < 4; j++) {
            int m = bm + ty * 4 + i, n = bn + tx * 4 + j;
            if (m < NPTS && n < NPTS) {
                float sq = fmaxf(g_norms[m] + g_norms[n] - 2.f * acc[i][j], 0.f);
                float v = (m == n) ? CUDART_INF_F : (1.0f / sqrtf(sq));
                g_Drec[(size_t)m * NPTS + n] = v;
                if (bi != bj) g_Drec[(size_t)n * NPTS + m] = v;   // mirror
            }
        }
    }
}

// =============== fp16 HMMA GEMM (R8-proven, projections only) ===============
#define BK 64
#define NC (K3 / BK)
#define SROW 144
#define STAGE_BYTES (2 * 128 * SROW)
#define GSMEM (2 * STAGE_BYTES)

__global__ __launch_bounds__(256) void mma_gemm_kernel(
    const __half* __restrict__ A, const __half* __restrict__ B,
    float* __restrict__ C, int M, int Nn,
    const float* __restrict__ bias, const int* __restrict__ rowIdx)
{
    extern __shared__ char smem[];
    const uint32_t sb = smem_u32(smem);
    const int tid = threadIdx.x;
    const int wid = tid >> 5;
    const int lid = tid & 31;
    const int bm = blockIdx.y * 128;
    const int bn = blockIdx.x * 128;

    const __half* gsrc[8];
    uint32_t sdst[8];
#pragma unroll
    for (int i = 0; i < 8; i++) {
        int u = tid + i * 256;
        int mat = u >> 10;
        int r = (u >> 3) & 127;
        int q = u & 7;
        int grow;
        if (mat == 0) {
            grow = bm + r; if (grow > M - 1) grow = M - 1;
            if (rowIdx) grow = rowIdx[grow];
            gsrc[i] = A + (size_t)grow * K3 + q * 8;
        } else {
            grow = bn + r; if (grow > Nn - 1) grow = Nn - 1;
            gsrc[i] = B + (size_t)grow * K3 + q * 8;
        }
        sdst[i] = sb + (uint32_t)(mat * 128 * SROW + r * SROW + q * 16);
    }

#pragma unroll
    for (int i = 0; i < 8; i++) CP_ASYNC16(sdst[i], gsrc[i]);
    CP_COMMIT();
#pragma unroll
    for (int i = 0; i < 8; i++) CP_ASYNC16(sdst[i] + STAGE_BYTES, gsrc[i] + BK);
    CP_COMMIT();

    const int wm = (wid >> 2) * 64;
    const int wn = (wid & 3) * 32;
    float c[4][4][4] = {};

    const uint32_t aAddrBase = sb + (uint32_t)((wm + (lid & 15)) * SROW + (lid >> 4) * 16);
    const uint32_t bAddrBase = sb + (uint32_t)(128 * SROW + (wn + (lid >> 4) * 8 + (lid & 7)) * SROW + ((lid >> 3) & 1) * 16);

    for (int kc = 0; kc < NC; kc++) {
        if (kc == NC - 1) { CP_WAIT0(); } else { CP_WAIT1(); }
        __syncthreads();
        const uint32_t stg = (uint32_t)(kc & 1) * STAGE_BYTES;
#pragma unroll
        for (int ks = 0; ks < 4; ks++) {
            const uint32_t kb = ks * 32;
            uint32_t a[4][4];
#pragma unroll
            for (int mt = 0; mt < 4; mt++)
                LDMATRIX_X4(a[mt][0], a[mt][1], a[mt][2], a[mt][3],
                            aAddrBase + stg + mt * (16 * SROW) + kb);
#pragma unroll
            for (int nt2 = 0; nt2 < 2; nt2++) {
                uint32_t b0, b1, b2, b3;
                LDMATRIX_X4(b0, b1, b2, b3, bAddrBase + stg + nt2 * (16 * SROW) + kb);
#pragma unroll
                for (int mt = 0; mt < 4; mt++) {
                    MMA16816(c[mt][nt2 * 2 + 0], a[mt], b0, b1);
                    MMA16816(c[mt][nt2 * 2 + 1], a[mt], b2, b3);
                }
            }
        }
        __syncthreads();
        if (kc + 2 < NC) {
#pragma unroll
            for (int i = 0; i < 8; i++)
                CP_ASYNC16(sdst[i] + stg, gsrc[i] + (kc + 2) * BK);
            CP_COMMIT();
        }
    }

    const int er = lid >> 2;
    const int ec = (lid & 3) * 2;
#pragma unroll
    for (int mt = 0; mt < 4; mt++) {
#pragma unroll
        for (int nt = 0; nt < 4; nt++) {
#pragma unroll
            for (int half = 0; half < 2; half++) {
                int m = bm + wm + mt * 16 + er + half * 8;
                int n = bn + wn + nt * 8 + ec;
                if (m < M && n < Nn) {
                    float v0 = c[mt][nt][half * 2 + 0];
                    float v1 = c[mt][nt][half * 2 + 1];
                    if (bias) { v0 += bias[n]; v1 += bias[n + 1]; }
                    *(float2*)&C[(size_t)m * Nn + n] = make_float2(v0, v1);
                }
            }
        }
    }
}

// ---------------- sequential greedy FPS (single CTA, float4 rows) ----------------
// ds layout: thread owns j = tid*4..tid*4+3 (seg0) and 4096+tid*4..+3 (seg1, tid<476).
__global__ __launch_bounds__(1024) void fps_kernel()
{
    const int tid = threadIdx.x;
    const bool v1 = (tid < 476);                   // 4096 + 476*4 = 6000 exactly
    const int b0 = tid * 4;
    const int b1 = 4096 + tid * 4;
    float4 d0 = *(const float4*)&g_Drec[b0];
    float4 d1 = v1 ? *(const float4*)&g_Drec[b1]
                   : make_float4(CUDART_INF_F, CUDART_INF_F, CUDART_INF_F, CUDART_INF_F);
    if (tid == 0) g_idx[0] = 0;
    __shared__ float swv[32];
    __shared__ int   swi[32];
    __shared__ int   sbest;
    for (int it = 1; it < KSEL; it++) {
        // local argmin over 8 values, ascending index order, strict < keeps lowest
        float bv = d0.x; int bi = b0;
        if (d0.y < bv) { bv = d0.y; bi = b0 + 1; }
        if (d0.z < bv) { bv = d0.z; bi = b0 + 2; }
        if (d0.w < bv) { bv = d0.w; bi = b0 + 3; }
        if (d1.x < bv) { bv = d1.x; bi = b1; }
        if (d1.y < bv) { bv = d1.y; bi = b1 + 1; }
        if (d1.z < bv) { bv = d1.z; bi = b1 + 2; }
        if (d1.w < bv) { bv = d1.w; bi = b1 + 3; }
#pragma unroll
        for (int o = 16; o > 0; o >>= 1) {
            float ov = __shfl_down_sync(0xffffffffu, bv, o);
            int   oi = __shfl_down_sync(0xffffffffu, bi, o);
            if (ov < bv || (ov == bv && oi < bi)) { bv = ov; bi = oi; }
        }
        int lane = tid & 31, wid = tid >> 5;
        if (lane == 0) { swv[wid] = bv; swi[wid] = bi; }
        __syncthreads();
        if (wid == 0) {
            bv = swv[lane]; bi = swi[lane];
#pragma unroll
            for (int o = 16; o > 0; o >>= 1) {
                float ov = __shfl_down_sync(0xffffffffu, bv, o);
                int   oi = __shfl_down_sync(0xffffffffu, bi, o);
                if (ov < bv || (ov == bv && oi < bi)) { bv = ov; bi = oi; }
            }
            if (lane == 0) { sbest = bi; g_idx[it] = bi; }
        }
        __syncthreads();
        const float* rowp = g_Drec + (size_t)sbest * NPTS;
        float4 r0 = *(const float4*)&rowp[b0];
        d0.x += r0.x; d0.y += r0.y; d0.z += r0.z; d0.w += r0.w;
        if (v1) {
            float4 r1 = *(const float4*)&rowp[b1];
            d1.x += r1.x; d1.y += r1.y; d1.z += r1.z; d1.w += r1.w;
        }
    }
}

// ---------------- aff[k,g,n] = (q_kg · kk_ng) / 8 ----------------
__global__ __launch_bounds__(256) void aff_kernel(const float* __restrict__ q,
                                                  const float* __restrict__ kk,
                                                  float* __restrict__ W)
{
    int g  = blockIdx.z;
    int k0 = blockIdx.y * 32;
    int n0 = blockIdx.x * 128;
    __shared__ float Qs[DG][32];
    __shared__ float Ks[DG][128];
    int tid = threadIdx.x;
#pragma unroll
    for (int it = 0; it < 2; it++) {
        int idx = tid + it * 256;
        int r = idx >> 4, c4 = (idx & 15) * 4;
        float4 v = make_float4(0.f, 0.f, 0.f, 0.f);
        if (k0 + r < KSEL) v = *(const float4*)(q + (size_t)(k0 + r) * DIM + g * DG + c4);
        Qs[c4 + 0][r] = v.x; Qs[c4 + 1][r] = v.y; Qs[c4 + 2][r] = v.z; Qs[c4 + 3][r] = v.w;
    }
#pragma unroll
    for (int it = 0; it < 8; it++) {
        int idx = tid + it * 256;
        int r = idx >> 4, c4 = (idx & 15) * 4;
        float4 v = make_float4(0.f, 0.f, 0.f, 0.f);
        if (n0 + r < NPTS) v = *(const float4*)(kk + (size_t)(n0 + r) * DIM + g * DG + c4);
        Ks[c4 + 0][r] = v.x; Ks[c4 + 1][r] = v.y; Ks[c4 + 2][r] = v.z; Ks[c4 + 3][r] = v.w;
    }
    __syncthreads();
    int tx = tid & 31;
    int ty = tid >> 5;
    float acc[4][4] = {};
#pragma unroll 16
    for (int d = 0; d < DG; d++) {
        float4 a = *(const float4*)&Qs[d][ty * 4];
        float4 b = *(const float4*)&Ks[d][tx * 4];
        acc[0][0] = fmaf(a.x, b.x, acc[0][0]); acc[0][1] = fmaf(a.x, b.y, acc[0][1]);
        acc[0][2] = fmaf(a.x, b.z, acc[0][2]); acc[0][3] = fmaf(a.x, b.w, acc[0][3]);
        acc[1][0] = fmaf(a.y, b.x, acc[1][0]); acc[1][1] = fmaf(a.y, b.y, acc[1][1]);
        acc[1][2] = fmaf(a.y, b.z, acc[1][2]); acc[1][3] = fmaf(a.y, b.w, acc[1][3]);
        acc[2][0] = fmaf(a.z, b.x, acc[2][0]); acc[2][1] = fmaf(a.z, b.y, acc[2][1]);
        acc[2][2] = fmaf(a.z, b.z, acc[2][2]); acc[2][3] = fmaf(a.z, b.w, acc[2][3]);
        acc[3][0] = fmaf(a.w, b.x, acc[3][0]); acc[3][1] = fmaf(a.w, b.y, acc[3][1]);
        acc[3][2] = fmaf(a.w, b.z, acc[3][2]); acc[3][3] = fmaf(a.w, b.w, acc[3][3]);
    }
#pragma unroll
    for (int i = 0; i < 4; i++) {
#pragma unroll
        for (int j = 0; j < 4; j++) {
            int k = k0 + ty * 4 + i, n = n0 + tx * 4 + j;
            if (k < KSEL && n < NPTS)
                W[((size_t)k * NG + g) * NPTS + n] = acc[i][j] * 0.125f;
        }
    }
}

// ---------------- position embedding + gate ----------------
__global__ __launch_bounds__(256) void logits_kernel(const float* __restrict__ bboxes,
                                                     const float* __restrict__ Wg,
                                                     const float* __restrict__ bg,
                                                     float* __restrict__ W)
{
    int k = blockIdx.y;
    int tid = threadIdx.x;
    int n = blockIdx.x * 256 + tid;
    __shared__ float sWg[NG][64];
    __shared__ float sbg[NG];
    __shared__ float qb[4];
    for (int i = tid; i < NG * 64; i += 256) sWg[i >> 6][i & 63] = Wg[i];
    if (tid < NG) sbg[tid] = bg[tid];
    if (tid == 0) {
        int qi = g_idx[k];
        float x1 = bboxes[qi * 4 + 0], y1 = bboxes[qi * 4 + 1];
        float x2 = bboxes[qi * 4 + 2], y2 = bboxes[qi * 4 + 3];
        qb[0] = x2 - x1 + 1.f; qb[1] = y2 - y1 + 1.f;
        qb[2] = 0.5f * (x1 + x2); qb[3] = 0.5f * (y1 + y2);
    }
    __syncthreads();
    if (n >= NPTS) return;
    float4 bb = *(const float4*)(bboxes + (size_t)n * 4);
    float wr = bb.z - bb.x + 1.f, hr = bb.w - bb.y + 1.f;
    float cxr = 0.5f * (bb.x + bb.z), cyr = 0.5f * (bb.y + bb.w);
    float w = qb[0], h = qb[1], cx = qb[2], cy = qb[3];
    float pos[4];
    pos[0] = logf(fabsf((cx - cxr) / w) + 1e-3f);
    pos[1] = logf(fabsf((cy - cyr) / h) + 1e-3f);
    pos[2] = logf(w / wr);
    pos[3] = logf(h / hr);
    const float dimmat[8] = { 1.0f, 2.3713737057f, 5.6234132519f, 13.3352143216f,
                              31.6227766017f, 74.9894209332f, 177.8279410039f, 421.6965034286f };
    float gw[NG];
#pragma unroll
    for (int g = 0; g < NG; g++) gw[g] = sbg[g];
#pragma unroll
    for (int c = 0; c < 4; c++) {
        float p100 = pos[c] * 100.f;
#pragma unroll
        for (int f = 0; f < 8; f++) {
            float arg = p100 / dimmat[f];
            float s, co;
            sincosf(arg, &s, &co);
#pragma unroll
            for (int g = 0; g < NG; g++) {
                gw[g] = fmaf(sWg[g][c * 16 + f],     s,  gw[g]);
                gw[g] = fmaf(sWg[g][c * 16 + 8 + f], co, gw[g]);
            }
        }
    }
    size_t base = ((size_t)k * NG) * NPTS + n;
#pragma unroll
    for (int g = 0; g < NG; g++) {
        float awt = fmaxf(gw[g], 0.f);
        W[base + (size_t)g * NPTS] += logf(awt + 1e-6f);
    }
}

// ---------------- softmax over n ----------------
__global__ __launch_bounds__(256) void softmax_kernel(float* __restrict__ W)
{
    __shared__ float buf[NPTS];
    __shared__ float sred[9];
    size_t base = (size_t)blockIdx.x * NPTS;
    int tid = threadIdx.x;
    float mx = -CUDART_INF_F;
    for (int i = tid; i < NPTS; i += 256) { float v = W[base + i]; buf[i] = v; mx = fmaxf(mx, v); }
    for (int o = 16; o > 0; o >>= 1) mx = fmaxf(mx, __shfl_down_sync(0xffffffffu, mx, o));
    if ((tid & 31) == 0) sred[tid >> 5] = mx;
    __syncthreads();
    if (tid == 0) { float m = sred[0]; for (int i = 1; i < 8; i++) m = fmaxf(m, sred[i]); sred[8] = m; }
    __syncthreads();
    mx = sred[8];
    float sum = 0.f;
    for (int i = tid; i < NPTS; i += 256) { float e = expf(buf[i] - mx); buf[i] = e; sum += e; }
    for (int o = 16; o > 0; o >>= 1) sum += __shfl_down_sync(0xffffffffu, sum, o);
    __syncthreads();
    if ((tid & 31) == 0) sred[tid >> 5] = sum;
    __syncthreads();
    if (tid == 0) { float t = 0.f; for (int i = 0; i < 8; i++) t += sred[i]; sred[8] = t; }
    __syncthreads();
    float inv = 1.0f / sred[8];
    for (int i = tid; i < NPTS; i += 256) W[base + i] = buf[i] * inv;
}

// ---------------- out[k, g*64+o] = sum_n soft[k,g,n] * V[n,g,o] + bv ----------------
// k-tile 32 (halves V re-reads vs k-tile 16); n-accumulation order unchanged.
__global__ __launch_bounds__(256) void out_kernel(const float* __restrict__ W,
                                                  const float* __restrict__ V,
                                                  const float* __restrict__ bv,
                                                  float* __restrict__ out)
{
    int g  = blockIdx.y;
    int k0 = blockIdx.x * 32;
    __shared__ float Ss[32][64];
    __shared__ float Vs[64][65];
    int tid = threadIdx.x;
    int o  = tid & 63;
    int ks = tid >> 6;                       // 0..3, each handles 8 k rows
    float acc[8] = {};
    for (int n0 = 0; n0 < NPTS; n0 += 64) {
#pragma unroll
        for (int it = 0; it < 8; it++) {
            int idx = tid + it * 256;        // 0..2047
            int r = idx >> 6, c = idx & 63;
            int kq = k0 + r, nn = n0 + c;
            Ss[r][c] = (kq < KSEL && nn < NPTS) ? W[((size_t)kq * NG + g) * NPTS + nn] : 0.f;
        }
#pragma unroll
        for (int it = 0; it < 16; it++) {
            int idx = tid + it * 256;        // 0..4095
            int r = idx >> 6, c = idx & 63;
            int nn = n0 + r;
            Vs[r][c] = (nn < NPTS) ? V[(size_t)nn * DIM + g * DG + c] : 0.f;
        }
        __syncthreads();
#pragma unroll
        for (int n = 0; n < 64; n++) {
            float v = Vs[n][o];
#pragma unroll
            for (int i = 0; i < 8; i++) acc[i] = fmaf(Ss[ks * 8 + i][n], v, acc[i]);
        }
        __syncthreads();
    }
#pragma unroll
    for (int i = 0; i < 8; i++) {
        int kq = k0 + ks * 8 + i;
        if (kq < KSEL) out[(size_t)kq * DIM + g * DG + o] = acc[i] + bv[g * DG + o];
    }
}

// ---------------- launch ----------------
extern "C" void kernel_launch(void* const* d_in, const int* in_sizes, int n_in,
                              void* d_out, int out_size)
{
    (void)in_sizes; (void)n_in; (void)out_size;
    const float* merged = (const float*)d_in[0];
    const float* bboxes = (const float*)d_in[1];
    const float* Wq     = (const float*)d_in[2];
    const float* bq     = (const float*)d_in[3];
    const float* Wk     = (const float*)d_in[4];
    const float* bk     = (const float*)d_in[5];
    const float* Wg     = (const float*)d_in[6];
    const float* bg     = (const float*)d_in[7];
    const float* Wv     = (const float*)d_in[8];
    const float* bv     = (const float*)d_in[9];
    float* out = (float*)d_out;

    float *p_q, *p_kk, *p_V, *p_W;
    int* p_idx;
    __half *p_Xa, *p_Wqs, *p_Wks, *p_Wvs;
    cudaGetSymbolAddress((void**)&p_q,   g_q);
    cudaGetSymbolAddress((void**)&p_kk,  g_kk);
    cudaGetSymbolAddress((void**)&p_V,   g_V);
    cudaGetSymbolAddress((void**)&p_W,   g_W);
    cudaGetSymbolAddress((void**)&p_idx, g_idx);
    cudaGetSymbolAddress((void**)&p_Xa,  g_Xa);
    cudaGetSymbolAddress((void**)&p_Wqs, g_Wqs);
    cudaGetSymbolAddress((void**)&p_Wks, g_Wks);
    cudaGetSymbolAddress((void**)&p_Wvs, g_Wvs);

    cudaFuncSetAttribute(mma_gemm_kernel, cudaFuncAttributeMaxDynamicSharedMemorySize, GSMEM);

    // 0) fp16 3-term splits (X gets A-pattern; weights get B-pattern)
    split3_kernel<<<(NPTS * DIM + 255) / 256, 256>>>(merged, p_Xa, nullptr, NPTS);
    split3_kernel<<<(DIM * DIM + 255) / 256, 256>>>(Wq, nullptr, p_Wqs, DIM);
    split3_kernel<<<(DIM * DIM + 255) / 256, 256>>>(Wk, nullptr, p_Wks, DIM);
    split3_kernel<<<(DIM * DIM + 255) / 256, 256>>>(Wv, nullptr, p_Wvs, DIM);

    // 1) norms + Drec via fp32 SIMT (bit-identical to R8; pipelined loads)
    norms_kernel<<<NPTS, 256>>>(merged);
    sgemm_drec_sym_kernel<<<dim3(94, 94), 256>>>(merged);

    // 2) sequential greedy FPS (float4; identical values & tie-break)
    fps_kernel<<<1, 1024>>>();

    // 3) projections via proven HMMA (q gathered, kk, V)
    mma_gemm_kernel<<<dim3(8, 3),  256, GSMEM>>>(p_Xa, p_Wqs, p_q,  KSEL, DIM, bq, p_idx);
    mma_gemm_kernel<<<dim3(8, 47), 256, GSMEM>>>(p_Xa, p_Wks, p_kk, NPTS, DIM, bk, nullptr);
    mma_gemm_kernel<<<dim3(8, 47), 256, GSMEM>>>(p_Xa, p_Wvs, p_V,  NPTS, DIM, nullptr, nullptr);

    // 4) attention: logits, softmax, weighted sum
    aff_kernel<<<dim3(47, 10, NG), 256>>>(p_q, p_kk, p_W);
    logits_kernel<<<dim3(24, KSEL), 256>>>(bboxes, Wg, bg, p_W);
    softmax_kernel<<<KSEL * NG, 256>>>(p_W);
    out_kernel<<<dim3(10, NG), 256>>>(p_W, p_V, bv, out);
}

// round 15
// speedup vs baseline: 1.5420x; 1.0044x over previous
#include <cuda_runtime.h>
#include <cuda_fp16.h>
#include <math.h>
#include <math_constants.h>
#include <stdint.h>

#define NPTS 6000
#define DIM  1024
#define K3   3072
#define NG   16
#define DG   64
#define KSEL 300

// ---------------- scratch (device globals; no allocation allowed) ----------------
static __device__ float g_norms[NPTS];
static __device__ float g_Drec[(size_t)NPTS * NPTS];          // 144 MB
static __device__ int   g_idx[KSEL];
static __device__ float g_q[KSEL * DIM];
static __device__ float g_kk[(size_t)NPTS * DIM];
static __device__ float g_V[(size_t)NPTS * DIM];
static __device__ float g_W[(size_t)KSEL * NG * NPTS];        // 115 MB logits/soft
static __device__ __half g_Xa[(size_t)NPTS * K3];             // [h | l | h]
static __device__ __half g_Wqs[(size_t)DIM * K3];             // [h | h | l]
static __device__ __half g_Wks[(size_t)DIM * K3];
static __device__ __half g_Wvs[(size_t)DIM * K3];

__device__ __forceinline__ uint32_t smem_u32(const void* p) {
    uint32_t a;
    asm("{ .reg .u64 t; cvta.to.shared.u64 t, %1; cvt.u32.u64 %0, t; }" : "=r"(a) : "l"(p));
    return a;
}
#define CP_ASYNC16(dst, src) \
    asm volatile("cp.async.cg.shared.global [%0], [%1], 16;" :: "r"(dst), "l"(src))
#define CP_COMMIT() asm volatile("cp.async.commit_group;")
#define CP_WAIT1()  asm volatile("cp.async.wait_group 1;")
#define CP_WAIT0()  asm volatile("cp.async.wait_group 0;")
#define LDMATRIX_X4(r0, r1, r2, r3, a) \
    asm volatile("ldmatrix.sync.aligned.m8n8.x4.shared.b16 {%0,%1,%2,%3}, [%4];" \
        : "=r"(r0), "=r"(r1), "=r"(r2), "=r"(r3) : "r"(a))
#define MMA16816(c, a, b0, b1) \
    asm volatile("mma.sync.aligned.m16n8k16.row.col.f32.f16.f16.f32 " \
        "{%0,%1,%2,%3}, {%4,%5,%6,%7}, {%8,%9}, {%0,%1,%2,%3};" \
        : "+f"((c)[0]), "+f"((c)[1]), "+f"((c)[2]), "+f"((c)[3]) \
        : "r"((a)[0]), "r"((a)[1]), "r"((a)[2]), "r"((a)[3]), "r"(b0), "r"(b1))

// ---------------- 3-term fp16 split for X (A-pattern [h|l|h]) -------------------
__global__ __launch_bounds__(256) void splitX_kernel(const float* __restrict__ X) {
    size_t i = (size_t)blockIdx.x * 256 + threadIdx.x;
    if (i >= (size_t)NPTS * DIM) return;
    size_t r = i / DIM, c = i % DIM;
    float x = X[i];
    __half h = __float2half(x);
    __half l = __float2half(x - __half2float(h));
    g_Xa[r * K3 + c]            = h;
    g_Xa[r * K3 + DIM + c]      = l;
    g_Xa[r * K3 + 2 * DIM + c]  = h;
}

// ---------------- merged weight split (B-pattern [h|h|l]) for Wq/Wk/Wv ----------
__global__ __launch_bounds__(256) void splitW_kernel(const float* __restrict__ Wq,
                                                     const float* __restrict__ Wk,
                                                     const float* __restrict__ Wv) {
    size_t i = (size_t)blockIdx.x * 256 + threadIdx.x;
    if (i >= (size_t)DIM * DIM) return;
    const float* src = (blockIdx.y == 0) ? Wq : (blockIdx.y == 1) ? Wk : Wv;
    __half* dst = (blockIdx.y == 0) ? g_Wqs : (blockIdx.y == 1) ? g_Wks : g_Wvs;
    size_t r = i / DIM, c = i % DIM;
    float x = src[i];
    __half h = __float2half(x);
    __half l = __float2half(x - __half2float(h));
    dst[r * K3 + c]            = h;
    dst[r * K3 + DIM + c]      = h;
    dst[r * K3 + 2 * DIM + c]  = l;
}

// ---------------- row squared-norms ----------------
__global__ __launch_bounds__(256) void norms_kernel(const float* __restrict__ X) {
    int r = blockIdx.x;
    const float* x = X + (size_t)r * DIM;
    float s = 0.f;
    for (int c = threadIdx.x; c < DIM; c += 256) { float v = x[c]; s = fmaf(v, v, s); }
    __shared__ float sred[8];
    for (int o = 16; o > 0; o >>= 1) s += __shfl_down_sync(0xffffffffu, s, o);
    if ((threadIdx.x & 31) == 0) sred[threadIdx.x >> 5] = s;
    __syncthreads();
    if (threadIdx.x == 0) {
        float t = 0.f;
        for (int i = 0; i < 8; i++) t += sred[i];
        g_norms[r] = t;
    }
}

// ------ symmetric fp32 Drec GEMM (R8 math, software-pipelined loads) ------
__global__ __launch_bounds__(256) void sgemm_drec_sym_kernel(const float* __restrict__ A)
{
    const int bi = blockIdx.y, bj = blockIdx.x;
    if (bj < bi) return;
    __shared__ float As[16][64];
    __shared__ float Bs[16][64];
    int tid = threadIdx.x;
    int bm = bi * 64, bn = bj * 64;
    int row = tid >> 2;
    int c4  = (tid & 3) * 4;
    int tx = tid & 15, ty = tid >> 4;
    float acc[4][4] = {};
    int am = bm + row, bnr = bn + row;
    const float* ap = (am  < NPTS) ? (A + (size_t)am  * DIM + c4) : nullptr;
    const float* bp = (bnr < NPTS) ? (A + (size_t)bnr * DIM + c4) : nullptr;

    float4 av = ap ? *(const float4*)ap : make_float4(0.f, 0.f, 0.f, 0.f);
    float4 bv = bp ? *(const float4*)bp : make_float4(0.f, 0.f, 0.f, 0.f);

    for (int k0 = 0; k0 < DIM; k0 += 16) {
        As[c4 + 0][row] = av.x; As[c4 + 1][row] = av.y; As[c4 + 2][row] = av.z; As[c4 + 3][row] = av.w;
        Bs[c4 + 0][row] = bv.x; Bs[c4 + 1][row] = bv.y; Bs[c4 + 2][row] = bv.z; Bs[c4 + 3][row] = bv.w;
        __syncthreads();
        if (k0 + 16 < DIM) {
            if (ap) av = *(const float4*)(ap + k0 + 16);
            if (bp) bv = *(const float4*)(bp + k0 + 16);
        }
#pragma unroll
        for (int kk = 0; kk < 16; kk++) {
            float4 a = *(const float4*)&As[kk][ty * 4];
            float4 b = *(const float4*)&Bs[kk][tx * 4];
            acc[0][0] = fmaf(a.x, b.x, acc[0][0]); acc[0][1] = fmaf(a.x, b.y, acc[0][1]);
            acc[0][2] = fmaf(a.x, b.z, acc[0][2]); acc[0][3] = fmaf(a.x, b.w, acc[0][3]);
            acc[1][0] = fmaf(a.y, b.x, acc[1][0]); acc[1][1] = fmaf(a.y, b.y, acc[1][1]);
            acc[1][2] = fmaf(a.y, b.z, acc[1][2]); acc[1][3] = fmaf(a.y, b.w, acc[1][3]);
            acc[2][0] = fmaf(a.z, b.x, acc[2][0]); acc[2][1] = fmaf(a.z, b.y, acc[2][1]);
            acc[2][2] = fmaf(a.z, b.z, acc[2][2]); acc[2][3] = fmaf(a.z, b.w, acc[2][3]);
            acc[3][0] = fmaf(a.w, b.x, acc[3][0]); acc[3][1] = fmaf(a.w, b.y, acc[3][1]);
            acc[3][2] = fmaf(a.w, b.z, acc[3][2]); acc[3][3] = fmaf(a.w, b.w, acc[3][3]);
        }
        __syncthreads();
    }
#pragma unroll
    for (int i = 0; i < 4; i++) {
#pragma unroll
        for (int j = 0; j < 4; j++) {
            int m = bm + ty * 4 + i, n = bn + tx * 4 + j;
            if (m < NPTS && n < NPTS) {
                float sq = fmaxf(g_norms[m] + g_norms[n] - 2.f * acc[i][j], 0.f);
                float v = (m == n) ? CUDART_INF_F : (1.0f / sqrtf(sq));
                g_Drec[(size_t)m * NPTS + n] = v;
                if (bi != bj) g_Drec[(size_t)n * NPTS + m] = v;
            }
        }
    }
}

// =============== fp16 HMMA GEMM (R8-proven, projections only) ===============
#define BK 64
#define NC (K3 / BK)
#define SROW 144
#define STAGE_BYTES (2 * 128 * SROW)
#define GSMEM (2 * STAGE_BYTES)

__global__ __launch_bounds__(256) void mma_gemm_kernel(
    const __half* __restrict__ A, const __half* __restrict__ B,
    float* __restrict__ C, int M, int Nn,
    const float* __restrict__ bias, const int* __restrict__ rowIdx)
{
    extern __shared__ char smem[];
    const uint32_t sb = smem_u32(smem);
    const int tid = threadIdx.x;
    const int wid = tid >> 5;
    const int lid = tid & 31;
    const int bm = blockIdx.y * 128;
    const int bn = blockIdx.x * 128;

    const __half* gsrc[8];
    uint32_t sdst[8];
#pragma unroll
    for (int i = 0; i < 8; i++) {
        int u = tid + i * 256;
        int mat = u >> 10;
        int r = (u >> 3) & 127;
        int q = u & 7;
        int grow;
        if (mat == 0) {
            grow = bm + r; if (grow > M - 1) grow = M - 1;
            if (rowIdx) grow = rowIdx[grow];
            gsrc[i] = A + (size_t)grow * K3 + q * 8;
        } else {
            grow = bn + r; if (grow > Nn - 1) grow = Nn - 1;
            gsrc[i] = B + (size_t)grow * K3 + q * 8;
        }
        sdst[i] = sb + (uint32_t)(mat * 128 * SROW + r * SROW + q * 16);
    }

#pragma unroll
    for (int i = 0; i < 8; i++) CP_ASYNC16(sdst[i], gsrc[i]);
    CP_COMMIT();
#pragma unroll
    for (int i = 0; i < 8; i++) CP_ASYNC16(sdst[i] + STAGE_BYTES, gsrc[i] + BK);
    CP_COMMIT();

    const int wm = (wid >> 2) * 64;
    const int wn = (wid & 3) * 32;
    float c[4][4][4] = {};

    const uint32_t aAddrBase = sb + (uint32_t)((wm + (lid & 15)) * SROW + (lid >> 4) * 16);
    const uint32_t bAddrBase = sb + (uint32_t)(128 * SROW + (wn + (lid >> 4) * 8 + (lid & 7)) * SROW + ((lid >> 3) & 1) * 16);

    for (int kc = 0; kc < NC; kc++) {
        if (kc == NC - 1) { CP_WAIT0(); } else { CP_WAIT1(); }
        __syncthreads();
        const uint32_t stg = (uint32_t)(kc & 1) * STAGE_BYTES;
#pragma unroll
        for (int ks = 0; ks < 4; ks++) {
            const uint32_t kb = ks * 32;
            uint32_t a[4][4];
#pragma unroll
            for (int mt = 0; mt < 4; mt++)
                LDMATRIX_X4(a[mt][0], a[mt][1], a[mt][2], a[mt][3],
                            aAddrBase + stg + mt * (16 * SROW) + kb);
#pragma unroll
            for (int nt2 = 0; nt2 < 2; nt2++) {
                uint32_t b0, b1, b2, b3;
                LDMATRIX_X4(b0, b1, b2, b3, bAddrBase + stg + nt2 * (16 * SROW) + kb);
#pragma unroll
                for (int mt = 0; mt < 4; mt++) {
                    MMA16816(c[mt][nt2 * 2 + 0], a[mt], b0, b1);
                    MMA16816(c[mt][nt2 * 2 + 1], a[mt], b2, b3);
                }
            }
        }
        __syncthreads();
        if (kc + 2 < NC) {
#pragma unroll
            for (int i = 0; i < 8; i++)
                CP_ASYNC16(sdst[i] + stg, gsrc[i] + (kc + 2) * BK);
            CP_COMMIT();
        }
    }

    const int er = lid >> 2;
    const int ec = (lid & 3) * 2;
#pragma unroll
    for (int mt = 0; mt < 4; mt++) {
#pragma unroll
        for (int nt = 0; nt < 4; nt++) {
#pragma unroll
            for (int half = 0; half < 2; half++) {
                int m = bm + wm + mt * 16 + er + half * 8;
                int n = bn + wn + nt * 8 + ec;
                if (m < M && n < Nn) {
                    float v0 = c[mt][nt][half * 2 + 0];
                    float v1 = c[mt][nt][half * 2 + 1];
                    if (bias) { v0 += bias[n]; v1 += bias[n + 1]; }
                    *(float2*)&C[(size_t)m * Nn + n] = make_float2(v0, v1);
                }
            }
        }
    }
}

// ---------------- sequential greedy FPS (single CTA, float4 rows) ----------------
__global__ __launch_bounds__(1024) void fps_kernel()
{
    const int tid = threadIdx.x;
    const bool v1 = (tid < 476);
    const int b0 = tid * 4;
    const int b1 = 4096 + tid * 4;
    float4 d0 = *(const float4*)&g_Drec[b0];
    float4 d1 = v1 ? *(const float4*)&g_Drec[b1]
                   : make_float4(CUDART_INF_F, CUDART_INF_F, CUDART_INF_F, CUDART_INF_F);
    if (tid == 0) g_idx[0] = 0;
    __shared__ float swv[32];
    __shared__ int   swi[32];
    __shared__ int   sbest;
    for (int it = 1; it < KSEL; it++) {
        float bv = d0.x; int bi = b0;
        if (d0.y < bv) { bv = d0.y; bi = b0 + 1; }
        if (d0.z < bv) { bv = d0.z; bi = b0 + 2; }
        if (d0.w < bv) { bv = d0.w; bi = b0 + 3; }
        if (d1.x < bv) { bv = d1.x; bi = b1; }
        if (d1.y < bv) { bv = d1.y; bi = b1 + 1; }
        if (d1.z < bv) { bv = d1.z; bi = b1 + 2; }
        if (d1.w < bv) { bv = d1.w; bi = b1 + 3; }
#pragma unroll
        for (int o = 16; o > 0; o >>= 1) {
            float ov = __shfl_down_sync(0xffffffffu, bv, o);
            int   oi = __shfl_down_sync(0xffffffffu, bi, o);
            if (ov < bv || (ov == bv && oi < bi)) { bv = ov; bi = oi; }
        }
        int lane = tid & 31, wid = tid >> 5;
        if (lane == 0) { swv[wid] = bv; swi[wid] = bi; }
        __syncthreads();
        if (wid == 0) {
            bv = swv[lane]; bi = swi[lane];
#pragma unroll
            for (int o = 16; o > 0; o >>= 1) {
                float ov = __shfl_down_sync(0xffffffffu, bv, o);
                int   oi = __shfl_down_sync(0xffffffffu, bi, o);
                if (ov < bv || (ov == bv && oi < bi)) { bv = ov; bi = oi; }
            }
            if (lane == 0) { sbest = bi; g_idx[it] = bi; }
        }
        __syncthreads();
        const float* rowp = g_Drec + (size_t)sbest * NPTS;
        float4 r0 = *(const float4*)&rowp[b0];
        d0.x += r0.x; d0.y += r0.y; d0.z += r0.z; d0.w += r0.w;
        if (v1) {
            float4 r1 = *(const float4*)&rowp[b1];
            d1.x += r1.x; d1.y += r1.y; d1.z += r1.z; d1.w += r1.w;
        }
    }
}

// ---------------- aff[k,g,n] = (q_kg · kk_ng) / 8 ----------------
__global__ __launch_bounds__(256) void aff_kernel(const float* __restrict__ q,
                                                  const float* __restrict__ kk,
                                                  float* __restrict__ W)
{
    int g  = blockIdx.z;
    int k0 = blockIdx.y * 32;
    int n0 = blockIdx.x * 128;
    __shared__ float Qs[DG][32];
    __shared__ float Ks[DG][128];
    int tid = threadIdx.x;
#pragma unroll
    for (int it = 0; it < 2; it++) {
        int idx = tid + it * 256;
        int r = idx >> 4, c4 = (idx & 15) * 4;
        float4 v = make_float4(0.f, 0.f, 0.f, 0.f);
        if (k0 + r < KSEL) v = *(const float4*)(q + (size_t)(k0 + r) * DIM + g * DG + c4);
        Qs[c4 + 0][r] = v.x; Qs[c4 + 1][r] = v.y; Qs[c4 + 2][r] = v.z; Qs[c4 + 3][r] = v.w;
    }
#pragma unroll
    for (int it = 0; it < 8; it++) {
        int idx = tid + it * 256;
        int r = idx >> 4, c4 = (idx & 15) * 4;
        float4 v = make_float4(0.f, 0.f, 0.f, 0.f);
        if (n0 + r < NPTS) v = *(const float4*)(kk + (size_t)(n0 + r) * DIM + g * DG + c4);
        Ks[c4 + 0][r] = v.x; Ks[c4 + 1][r] = v.y; Ks[c4 + 2][r] = v.z; Ks[c4 + 3][r] = v.w;
    }
    __syncthreads();
    int tx = tid & 31;
    int ty = tid >> 5;
    float acc[4][4] = {};
#pragma unroll 16
    for (int d = 0; d < DG; d++) {
        float4 a = *(const float4*)&Qs[d][ty * 4];
        float4 b = *(const float4*)&Ks[d][tx * 4];
        acc[0][0] = fmaf(a.x, b.x, acc[0][0]); acc[0][1] = fmaf(a.x, b.y, acc[0][1]);
        acc[0][2] = fmaf(a.x, b.z, acc[0][2]); acc[0][3] = fmaf(a.x, b.w, acc[0][3]);
        acc[1][0] = fmaf(a.y, b.x, acc[1][0]); acc[1][1] = fmaf(a.y, b.y, acc[1][1]);
        acc[1][2] = fmaf(a.y, b.z, acc[1][2]); acc[1][3] = fmaf(a.y, b.w, acc[1][3]);
        acc[2][0] = fmaf(a.z, b.x, acc[2][0]); acc[2][1] = fmaf(a.z, b.y, acc[2][1]);
        acc[2][2] = fmaf(a.z, b.z, acc[2][2]); acc[2][3] = fmaf(a.z, b.w, acc[2][3]);
        acc[3][0] = fmaf(a.w, b.x, acc[3][0]); acc[3][1] = fmaf(a.w, b.y, acc[3][1]);
        acc[3][2] = fmaf(a.w, b.z, acc[3][2]); acc[3][3] = fmaf(a.w, b.w, acc[3][3]);
    }
#pragma unroll
    for (int i = 0; i < 4; i++) {
#pragma unroll
        for (int j = 0; j < 4; j++) {
            int k = k0 + ty * 4 + i, n = n0 + tx * 4 + j;
            if (k < KSEL && n < NPTS)
                W[((size_t)k * NG + g) * NPTS + n] = acc[i][j] * 0.125f;
        }
    }
}

// ======= fused gate + softmax: W[k,g,n] = gate*exp(aff) / sum_n =======
// softmax(log(relu(gate)+1e-6)+aff) == (relu(gate)+1e-6)*exp(aff)/sum — no logf needed.
__global__ __launch_bounds__(512) void gatesm_kernel(const float* __restrict__ bboxes,
                                                     const float* __restrict__ Wg,
                                                     const float* __restrict__ bg,
                                                     float* __restrict__ W)
{
    const int k = blockIdx.x;
    const int tid = threadIdx.x;
    __shared__ float sWg[NG][64];
    __shared__ float sbg[NG];
    __shared__ float qb[4];
    __shared__ float tot[NG];
    for (int i = tid; i < NG * 64; i += 512) sWg[i >> 6][i & 63] = Wg[i];
    if (tid < NG) { sbg[tid] = bg[tid]; tot[tid] = 0.f; }
    if (tid == 0) {
        int qi = g_idx[k];
        float x1 = bboxes[qi * 4 + 0], y1 = bboxes[qi * 4 + 1];
        float x2 = bboxes[qi * 4 + 2], y2 = bboxes[qi * 4 + 3];
        qb[0] = x2 - x1 + 1.f; qb[1] = y2 - y1 + 1.f;
        qb[2] = 0.5f * (x1 + x2); qb[3] = 0.5f * (y1 + y2);
    }
    __syncthreads();
    const float dimmat[8] = { 1.0f, 2.3713737057f, 5.6234132519f, 13.3352143216f,
                              31.6227766017f, 74.9894209332f, 177.8279410039f, 421.6965034286f };
    float gsum[NG];
#pragma unroll
    for (int g = 0; g < NG; g++) gsum[g] = 0.f;
    const float w = qb[0], h = qb[1], cx = qb[2], cy = qb[3];
    const size_t kbase = (size_t)k * NG * NPTS;

    for (int n = tid; n < NPTS; n += 512) {
        float4 bb = *(const float4*)(bboxes + (size_t)n * 4);
        float wr = bb.z - bb.x + 1.f, hr = bb.w - bb.y + 1.f;
        float cxr = 0.5f * (bb.x + bb.z), cyr = 0.5f * (bb.y + bb.w);
        float pos[4];
        pos[0] = logf(fabsf((cx - cxr) / w) + 1e-3f);
        pos[1] = logf(fabsf((cy - cyr) / h) + 1e-3f);
        pos[2] = logf(w / wr);
        pos[3] = logf(h / hr);
        float gw[NG];
#pragma unroll
        for (int g = 0; g < NG; g++) gw[g] = sbg[g];
#pragma unroll
        for (int c = 0; c < 4; c++) {
            float p100 = pos[c] * 100.f;
#pragma unroll
            for (int f = 0; f < 8; f++) {
                float arg = p100 / dimmat[f];
                float s, co;
                sincosf(arg, &s, &co);
#pragma unroll
                for (int g = 0; g < NG; g++) {
                    gw[g] = fmaf(sWg[g][c * 16 + f],     s,  gw[g]);
                    gw[g] = fmaf(sWg[g][c * 16 + 8 + f], co, gw[g]);
                }
            }
        }
#pragma unroll
        for (int g = 0; g < NG; g++) {
            size_t idx = kbase + (size_t)g * NPTS + n;
            float aw = fmaxf(gw[g], 0.f) + 1e-6f;
            float t = aw * __expf(W[idx]);
            W[idx] = t;
            gsum[g] += t;
        }
    }
    // block-reduce per-g sums
#pragma unroll
    for (int g = 0; g < NG; g++) {
        float s = gsum[g];
#pragma unroll
        for (int o = 16; o > 0; o >>= 1) s += __shfl_down_sync(0xffffffffu, s, o);
        if ((tid & 31) == 0) atomicAdd(&tot[g], s);
    }
    __syncthreads();
    float inv[NG];
#pragma unroll
    for (int g = 0; g < NG; g++) inv[g] = 1.0f / tot[g];
    for (int n = tid; n < NPTS; n += 512) {
#pragma unroll
        for (int g = 0; g < NG; g++) {
            size_t idx = kbase + (size_t)g * NPTS + n;
            W[idx] *= inv[g];
        }
    }
}

// ---------------- out[k, g*64+o] = sum_n soft[k,g,n] * V[n,g,o] + bv ----------------
__global__ __launch_bounds__(256) void out_kernel(const float* __restrict__ W,
                                                  const float* __restrict__ V,
                                                  const float* __restrict__ bv,
                                                  float* __restrict__ out)
{
    int g  = blockIdx.y;
    int k0 = blockIdx.x * 32;
    __shared__ float Ss[32][64];
    __shared__ float Vs[64][65];
    int tid = threadIdx.x;
    int o  = tid & 63;
    int ks = tid >> 6;
    float acc[8] = {};
    for (int n0 = 0; n0 < NPTS; n0 += 64) {
#pragma unroll
        for (int it = 0; it < 8; it++) {
            int idx = tid + it * 256;
            int r = idx >> 6, c = idx & 63;
            int kq = k0 + r, nn = n0 + c;
            Ss[r][c] = (kq < KSEL && nn < NPTS) ? W[((size_t)kq * NG + g) * NPTS + nn] : 0.f;
        }
#pragma unroll
        for (int it = 0; it < 16; it++) {
            int idx = tid + it * 256;
            int r = idx >> 6, c = idx & 63;
            int nn = n0 + r;
            Vs[r][c] = (nn < NPTS) ? V[(size_t)nn * DIM + g * DG + c] : 0.f;
        }
        __syncthreads();
#pragma unroll
        for (int n = 0; n < 64; n++) {
            float v = Vs[n][o];
#pragma unroll
            for (int i = 0; i < 8; i++) acc[i] = fmaf(Ss[ks * 8 + i][n], v, acc[i]);
        }
        __syncthreads();
    }
#pragma unroll
    for (int i = 0; i < 8; i++) {
        int kq = k0 + ks * 8 + i;
        if (kq < KSEL) out[(size_t)kq * DIM + g * DG + o] = acc[i] + bv[g * DG + o];
    }
}

// ---------------- launch ----------------
extern "C" void kernel_launch(void* const* d_in, const int* in_sizes, int n_in,
                              void* d_out, int out_size)
{
    (void)in_sizes; (void)n_in; (void)out_size;
    const float* merged = (const float*)d_in[0];
    const float* bboxes = (const float*)d_in[1];
    const float* Wq     = (const float*)d_in[2];
    const float* bq     = (const float*)d_in[3];
    const float* Wk     = (const float*)d_in[4];
    const float* bk     = (const float*)d_in[5];
    const float* Wg     = (const float*)d_in[6];
    const float* bg     = (const float*)d_in[7];
    const float* Wv     = (const float*)d_in[8];
    const float* bv     = (const float*)d_in[9];
    float* out = (float*)d_out;

    float *p_q, *p_kk, *p_V, *p_W;
    int* p_idx;
    __half *p_Xa, *p_Wqs, *p_Wks, *p_Wvs;
    cudaGetSymbolAddress((void**)&p_q,   g_q);
    cudaGetSymbolAddress((void**)&p_kk,  g_kk);
    cudaGetSymbolAddress((void**)&p_V,   g_V);
    cudaGetSymbolAddress((void**)&p_W,   g_W);
    cudaGetSymbolAddress((void**)&p_idx, g_idx);
    cudaGetSymbolAddress((void**)&p_Xa,  g_Xa);
    cudaGetSymbolAddress((void**)&p_Wqs, g_Wqs);
    cudaGetSymbolAddress((void**)&p_Wks, g_Wks);
    cudaGetSymbolAddress((void**)&p_Wvs, g_Wvs);

    cudaFuncSetAttribute(mma_gemm_kernel, cudaFuncAttributeMaxDynamicSharedMemorySize, GSMEM);

    // 0) fp16 3-term splits (X A-pattern; all three weights in one launch)
    splitX_kernel<<<(NPTS * DIM + 255) / 256, 256>>>(merged);
    splitW_kernel<<<dim3((DIM * DIM + 255) / 256, 3), 256>>>(Wq, Wk, Wv);

    // 1) norms + Drec via fp32 SIMT (bit-identical to R13)
    norms_kernel<<<NPTS, 256>>>(merged);
    sgemm_drec_sym_kernel<<<dim3(94, 94), 256>>>(merged);

    // 2) sequential greedy FPS
    fps_kernel<<<1, 1024>>>();

    // 3) projections via proven HMMA (q gathered, kk, V)
    mma_gemm_kernel<<<dim3(8, 3),  256, GSMEM>>>(p_Xa, p_Wqs, p_q,  KSEL, DIM, bq, p_idx);
    mma_gemm_kernel<<<dim3(8, 47), 256, GSMEM>>>(p_Xa, p_Wks, p_kk, NPTS, DIM, bk, nullptr);
    mma_gemm_kernel<<<dim3(8, 47), 256, GSMEM>>>(p_Xa, p_Wvs, p_V,  NPTS, DIM, nullptr, nullptr);

    // 4) attention: aff logits, fused gate+softmax (no logf), weighted sum
    aff_kernel<<<dim3(47, 10, NG), 256>>>(p_q, p_kk, p_W);
    gatesm_kernel<<<KSEL, 512>>>(bboxes, Wg, bg, p_W);
    out_kernel<<<dim3(10, NG), 256>>>(p_W, p_V, bv, out);
}

// round 16
// speedup vs baseline: 1.7179x; 1.1141x over previous
#include <cuda_runtime.h>
#include <cuda_fp16.h>
#include <math.h>
#include <math_constants.h>
#include <stdint.h>

#define NPTS 6000
#define DIM  1024
#define K3   3072
#define NG   16
#define DG   64
#define KSEL 300

// ---------------- scratch (device globals; no allocation allowed) ----------------
static __device__ float g_norms[NPTS];
static __device__ float g_Drec[(size_t)NPTS * NPTS];          // 144 MB
static __device__ int   g_idx[KSEL];
static __device__ float g_q[KSEL * DIM];
static __device__ float g_kk[(size_t)NPTS * DIM];
static __device__ float g_V[(size_t)NPTS * DIM];
static __device__ float g_W[(size_t)KSEL * NG * NPTS];        // 115 MB logits/soft
static __device__ __half g_Xa[(size_t)NPTS * K3];             // [h | l | h]
static __device__ __half g_Wqs[(size_t)DIM * K3];             // [h | h | l]
static __device__ __half g_Wks[(size_t)DIM * K3];
static __device__ __half g_Wvs[(size_t)DIM * K3];

__device__ __forceinline__ uint32_t smem_u32(const void* p) {
    uint32_t a;
    asm("{ .reg .u64 t; cvta.to.shared.u64 t, %1; cvt.u32.u64 %0, t; }" : "=r"(a) : "l"(p));
    return a;
}
#define CP_ASYNC16(dst, src) \
    asm volatile("cp.async.cg.shared.global [%0], [%1], 16;" :: "r"(dst), "l"(src))
#define CP_COMMIT() asm volatile("cp.async.commit_group;")
#define CP_WAIT1()  asm volatile("cp.async.wait_group 1;")
#define CP_WAIT0()  asm volatile("cp.async.wait_group 0;")
#define LDMATRIX_X4(r0, r1, r2, r3, a) \
    asm volatile("ldmatrix.sync.aligned.m8n8.x4.shared.b16 {%0,%1,%2,%3}, [%4];" \
        : "=r"(r0), "=r"(r1), "=r"(r2), "=r"(r3) : "r"(a))
#define MMA16816(c, a, b0, b1) \
    asm volatile("mma.sync.aligned.m16n8k16.row.col.f32.f16.f16.f32 " \
        "{%0,%1,%2,%3}, {%4,%5,%6,%7}, {%8,%9}, {%0,%1,%2,%3};" \
        : "+f"((c)[0]), "+f"((c)[1]), "+f"((c)[2]), "+f"((c)[3]) \
        : "r"((a)[0]), "r"((a)[1]), "r"((a)[2]), "r"((a)[3]), "r"(b0), "r"(b1))

// ---------------- 3-term fp16 split for X (A-pattern [h|l|h]) -------------------
__global__ __launch_bounds__(256) void splitX_kernel(const float* __restrict__ X) {
    size_t i = (size_t)blockIdx.x * 256 + threadIdx.x;
    if (i >= (size_t)NPTS * DIM) return;
    size_t r = i / DIM, c = i % DIM;
    float x = X[i];
    __half h = __float2half(x);
    __half l = __float2half(x - __half2float(h));
    g_Xa[r * K3 + c]            = h;
    g_Xa[r * K3 + DIM + c]      = l;
    g_Xa[r * K3 + 2 * DIM + c]  = h;
}

// ---------------- merged weight split (B-pattern [h|h|l]) for Wq/Wk/Wv ----------
__global__ __launch_bounds__(256) void splitW_kernel(const float* __restrict__ Wq,
                                                     const float* __restrict__ Wk,
                                                     const float* __restrict__ Wv) {
    size_t i = (size_t)blockIdx.x * 256 + threadIdx.x;
    if (i >= (size_t)DIM * DIM) return;
    const float* src = (blockIdx.y == 0) ? Wq : (blockIdx.y == 1) ? Wk : Wv;
    __half* dst = (blockIdx.y == 0) ? g_Wqs : (blockIdx.y == 1) ? g_Wks : g_Wvs;
    size_t r = i / DIM, c = i % DIM;
    float x = src[i];
    __half h = __float2half(x);
    __half l = __float2half(x - __half2float(h));
    dst[r * K3 + c]            = h;
    dst[r * K3 + DIM + c]      = h;
    dst[r * K3 + 2 * DIM + c]  = l;
}

// ---------------- row squared-norms ----------------
__global__ __launch_bounds__(256) void norms_kernel(const float* __restrict__ X) {
    int r = blockIdx.x;
    const float* x = X + (size_t)r * DIM;
    float s = 0.f;
    for (int c = threadIdx.x; c < DIM; c += 256) { float v = x[c]; s = fmaf(v, v, s); }
    __shared__ float sred[8];
    for (int o = 16; o > 0; o >>= 1) s += __shfl_down_sync(0xffffffffu, s, o);
    if ((threadIdx.x & 31) == 0) sred[threadIdx.x >> 5] = s;
    __syncthreads();
    if (threadIdx.x == 0) {
        float t = 0.f;
        for (int i = 0; i < 8; i++) t += sred[i];
        g_norms[r] = t;
    }
}

// ====== symmetric fp32 Drec GEMM, 128x128 block, 8x8 thread tile (FMA-bound) ======
// k accumulation order per output element identical to prior rounds => bit-identical.
#define DBK 16
__global__ __launch_bounds__(256) void drec128_kernel(const float* __restrict__ A)
{
    const int bi = blockIdx.y, bj = blockIdx.x;
    if (bj < bi) return;                      // upper triangle only
    __shared__ float As[DBK][128];
    __shared__ float Bs[DBK][128];
    const int tid = threadIdx.x;
    const int bm = bi * 128, bn = bj * 128;
    const int lrow = tid & 127;
    const int lk = (tid >> 7) * 8;            // 0 or 8
    const int tx = tid & 15, ty = tid >> 4;

    int arow = bm + lrow; if (arow > NPTS - 1) arow = NPTS - 1;
    int brow = bn + lrow; if (brow > NPTS - 1) brow = NPTS - 1;
    const float* apt = A + (size_t)arow * DIM + lk;
    const float* bpt = A + (size_t)brow * DIM + lk;

    float4 pa0 = *(const float4*)(apt);
    float4 pa1 = *(const float4*)(apt + 4);
    float4 pb0 = *(const float4*)(bpt);
    float4 pb1 = *(const float4*)(bpt + 4);

    float acc[2][2][4][4] = {};

    for (int k0 = 0; k0 < DIM; k0 += DBK) {
        As[lk + 0][lrow] = pa0.x; As[lk + 1][lrow] = pa0.y; As[lk + 2][lrow] = pa0.z; As[lk + 3][lrow] = pa0.w;
        As[lk + 4][lrow] = pa1.x; As[lk + 5][lrow] = pa1.y; As[lk + 6][lrow] = pa1.z; As[lk + 7][lrow] = pa1.w;
        Bs[lk + 0][lrow] = pb0.x; Bs[lk + 1][lrow] = pb0.y; Bs[lk + 2][lrow] = pb0.z; Bs[lk + 3][lrow] = pb0.w;
        Bs[lk + 4][lrow] = pb1.x; Bs[lk + 5][lrow] = pb1.y; Bs[lk + 6][lrow] = pb1.z; Bs[lk + 7][lrow] = pb1.w;
        __syncthreads();
        if (k0 + DBK < DIM) {
            pa0 = *(const float4*)(apt + k0 + DBK);
            pa1 = *(const float4*)(apt + k0 + DBK + 4);
            pb0 = *(const float4*)(bpt + k0 + DBK);
            pb1 = *(const float4*)(bpt + k0 + DBK + 4);
        }
#pragma unroll
        for (int kk = 0; kk < DBK; kk++) {
            float4 a0 = *(const float4*)&As[kk][ty * 4];
            float4 a1 = *(const float4*)&As[kk][64 + ty * 4];
            float4 b0 = *(const float4*)&Bs[kk][tx * 4];
            float4 b1 = *(const float4*)&Bs[kk][64 + tx * 4];
            const float ar[2][4] = { {a0.x, a0.y, a0.z, a0.w}, {a1.x, a1.y, a1.z, a1.w} };
            const float br[2][4] = { {b0.x, b0.y, b0.z, b0.w}, {b1.x, b1.y, b1.z, b1.w} };
#pragma unroll
            for (int ih = 0; ih < 2; ih++)
#pragma unroll
                for (int i = 0; i < 4; i++)
#pragma unroll
                    for (int jh = 0; jh < 2; jh++)
#pragma unroll
                        for (int j = 0; j < 4; j++)
                            acc[ih][jh][i][j] = fmaf(ar[ih][i], br[jh][j], acc[ih][jh][i][j]);
        }
        __syncthreads();
    }

#pragma unroll
    for (int ih = 0; ih < 2; ih++) {
#pragma unroll
        for (int i = 0; i < 4; i++) {
            int m = bm + ih * 64 + ty * 4 + i;
            if (m >= NPTS) continue;
            float nm = g_norms[m];
#pragma unroll
            for (int jh = 0; jh < 2; jh++) {
#pragma unroll
                for (int j = 0; j < 4; j++) {
                    int n = bn + jh * 64 + tx * 4 + j;
                    if (n < NPTS && n >= m) {
                        float sq = fmaxf(nm + g_norms[n] - 2.f * acc[ih][jh][i][j], 0.f);
                        float v = (m == n) ? CUDART_INF_F : (1.0f / sqrtf(sq));
                        g_Drec[(size_t)m * NPTS + n] = v;
                        if (n > m) g_Drec[(size_t)n * NPTS + m] = v;
                    }
                }
            }
        }
    }
}

// =============== fp16 HMMA GEMM (R8-proven, projections only) ===============
#define BK 64
#define NC (K3 / BK)
#define SROW 144
#define STAGE_BYTES (2 * 128 * SROW)
#define GSMEM (2 * STAGE_BYTES)

__global__ __launch_bounds__(256) void mma_gemm_kernel(
    const __half* __restrict__ A, const __half* __restrict__ B,
    float* __restrict__ C, int M, int Nn,
    const float* __restrict__ bias, const int* __restrict__ rowIdx)
{
    extern __shared__ char smem[];
    const uint32_t sb = smem_u32(smem);
    const int tid = threadIdx.x;
    const int wid = tid >> 5;
    const int lid = tid & 31;
    const int bm = blockIdx.y * 128;
    const int bn = blockIdx.x * 128;

    const __half* gsrc[8];
    uint32_t sdst[8];
#pragma unroll
    for (int i = 0; i < 8; i++) {
        int u = tid + i * 256;
        int mat = u >> 10;
        int r = (u >> 3) & 127;
        int q = u & 7;
        int grow;
        if (mat == 0) {
            grow = bm + r; if (grow > M - 1) grow = M - 1;
            if (rowIdx) grow = rowIdx[grow];
            gsrc[i] = A + (size_t)grow * K3 + q * 8;
        } else {
            grow = bn + r; if (grow > Nn - 1) grow = Nn - 1;
            gsrc[i] = B + (size_t)grow * K3 + q * 8;
        }
        sdst[i] = sb + (uint32_t)(mat * 128 * SROW + r * SROW + q * 16);
    }

#pragma unroll
    for (int i = 0; i < 8; i++) CP_ASYNC16(sdst[i], gsrc[i]);
    CP_COMMIT();
#pragma unroll
    for (int i = 0; i < 8; i++) CP_ASYNC16(sdst[i] + STAGE_BYTES, gsrc[i] + BK);
    CP_COMMIT();

    const int wm = (wid >> 2) * 64;
    const int wn = (wid & 3) * 32;
    float c[4][4][4] = {};

    const uint32_t aAddrBase = sb + (uint32_t)((wm + (lid & 15)) * SROW + (lid >> 4) * 16);
    const uint32_t bAddrBase = sb + (uint32_t)(128 * SROW + (wn + (lid >> 4) * 8 + (lid & 7)) * SROW + ((lid >> 3) & 1) * 16);

    for (int kc = 0; kc < NC; kc++) {
        if (kc == NC - 1) { CP_WAIT0(); } else { CP_WAIT1(); }
        __syncthreads();
        const uint32_t stg = (uint32_t)(kc & 1) * STAGE_BYTES;
#pragma unroll
        for (int ks = 0; ks < 4; ks++) {
            const uint32_t kb = ks * 32;
            uint32_t a[4][4];
#pragma unroll
            for (int mt = 0; mt < 4; mt++)
                LDMATRIX_X4(a[mt][0], a[mt][1], a[mt][2], a[mt][3],
                            aAddrBase + stg + mt * (16 * SROW) + kb);
#pragma unroll
            for (int nt2 = 0; nt2 < 2; nt2++) {
                uint32_t b0, b1, b2, b3;
                LDMATRIX_X4(b0, b1, b2, b3, bAddrBase + stg + nt2 * (16 * SROW) + kb);
#pragma unroll
                for (int mt = 0; mt < 4; mt++) {
                    MMA16816(c[mt][nt2 * 2 + 0], a[mt], b0, b1);
                    MMA16816(c[mt][nt2 * 2 + 1], a[mt], b2, b3);
                }
            }
        }
        __syncthreads();
        if (kc + 2 < NC) {
#pragma unroll
            for (int i = 0; i < 8; i++)
                CP_ASYNC16(sdst[i] + stg, gsrc[i] + (kc + 2) * BK);
            CP_COMMIT();
        }
    }

    const int er = lid >> 2;
    const int ec = (lid & 3) * 2;
#pragma unroll
    for (int mt = 0; mt < 4; mt++) {
#pragma unroll
        for (int nt = 0; nt < 4; nt++) {
#pragma unroll
            for (int half = 0; half < 2; half++) {
                int m = bm + wm + mt * 16 + er + half * 8;
                int n = bn + wn + nt * 8 + ec;
                if (m < M && n < Nn) {
                    float v0 = c[mt][nt][half * 2 + 0];
                    float v1 = c[mt][nt][half * 2 + 1];
                    if (bias) { v0 += bias[n]; v1 += bias[n + 1]; }
                    *(float2*)&C[(size_t)m * Nn + n] = make_float2(v0, v1);
                }
            }
        }
    }
}

// ---------------- sequential greedy FPS (single CTA, float4 rows) ----------------
__global__ __launch_bounds__(1024) void fps_kernel()
{
    const int tid = threadIdx.x;
    const bool v1 = (tid < 476);
    const int b0 = tid * 4;
    const int b1 = 4096 + tid * 4;
    float4 d0 = *(const float4*)&g_Drec[b0];
    float4 d1 = v1 ? *(const float4*)&g_Drec[b1]
                   : make_float4(CUDART_INF_F, CUDART_INF_F, CUDART_INF_F, CUDART_INF_F);
    if (tid == 0) g_idx[0] = 0;
    __shared__ float swv[32];
    __shared__ int   swi[32];
    __shared__ int   sbest;
    for (int it = 1; it < KSEL; it++) {
        float bv = d0.x; int bi = b0;
        if (d0.y < bv) { bv = d0.y; bi = b0 + 1; }
        if (d0.z < bv) { bv = d0.z; bi = b0 + 2; }
        if (d0.w < bv) { bv = d0.w; bi = b0 + 3; }
        if (d1.x < bv) { bv = d1.x; bi = b1; }
        if (d1.y < bv) { bv = d1.y; bi = b1 + 1; }
        if (d1.z < bv) { bv = d1.z; bi = b1 + 2; }
        if (d1.w < bv) { bv = d1.w; bi = b1 + 3; }
#pragma unroll
        for (int o = 16; o > 0; o >>= 1) {
            float ov = __shfl_down_sync(0xffffffffu, bv, o);
            int   oi = __shfl_down_sync(0xffffffffu, bi, o);
            if (ov < bv || (ov == bv && oi < bi)) { bv = ov; bi = oi; }
        }
        int lane = tid & 31, wid = tid >> 5;
        if (lane == 0) { swv[wid] = bv; swi[wid] = bi; }
        __syncthreads();
        if (wid == 0) {
            bv = swv[lane]; bi = swi[lane];
#pragma unroll
            for (int o = 16; o > 0; o >>= 1) {
                float ov = __shfl_down_sync(0xffffffffu, bv, o);
                int   oi = __shfl_down_sync(0xffffffffu, bi, o);
                if (ov < bv || (ov == bv && oi < bi)) { bv = ov; bi = oi; }
            }
            if (lane == 0) { sbest = bi; g_idx[it] = bi; }
        }
        __syncthreads();
        const float* rowp = g_Drec + (size_t)sbest * NPTS;
        float4 r0 = *(const float4*)&rowp[b0];
        d0.x += r0.x; d0.y += r0.y; d0.z += r0.z; d0.w += r0.w;
        if (v1) {
            float4 r1 = *(const float4*)&rowp[b1];
            d1.x += r1.x; d1.y += r1.y; d1.z += r1.z; d1.w += r1.w;
        }
    }
}

// ---------------- aff[k,g,n] = (q_kg · kk_ng) / 8 ----------------
__global__ __launch_bounds__(256) void aff_kernel(const float* __restrict__ q,
                                                  const float* __restrict__ kk,
                                                  float* __restrict__ W)
{
    int g  = blockIdx.z;
    int k0 = blockIdx.y * 32;
    int n0 = blockIdx.x * 128;
    __shared__ float Qs[DG][32];
    __shared__ float Ks[DG][128];
    int tid = threadIdx.x;
#pragma unroll
    for (int it = 0; it < 2; it++) {
        int idx = tid + it * 256;
        int r = idx >> 4, c4 = (idx & 15) * 4;
        float4 v = make_float4(0.f, 0.f, 0.f, 0.f);
        if (k0 + r < KSEL) v = *(const float4*)(q + (size_t)(k0 + r) * DIM + g * DG + c4);
        Qs[c4 + 0][r] = v.x; Qs[c4 + 1][r] = v.y; Qs[c4 + 2][r] = v.z; Qs[c4 + 3][r] = v.w;
    }
#pragma unroll
    for (int it = 0; it < 8; it++) {
        int idx = tid + it * 256;
        int r = idx >> 4, c4 = (idx & 15) * 4;
        float4 v = make_float4(0.f, 0.f, 0.f, 0.f);
        if (n0 + r < NPTS) v = *(const float4*)(kk + (size_t)(n0 + r) * DIM + g * DG + c4);
        Ks[c4 + 0][r] = v.x; Ks[c4 + 1][r] = v.y; Ks[c4 + 2][r] = v.z; Ks[c4 + 3][r] = v.w;
    }
    __syncthreads();
    int tx = tid & 31;
    int ty = tid >> 5;
    float acc[4][4] = {};
#pragma unroll 16
    for (int d = 0; d < DG; d++) {
        float4 a = *(const float4*)&Qs[d][ty * 4];
        float4 b = *(const float4*)&Ks[d][tx * 4];
        acc[0][0] = fmaf(a.x, b.x, acc[0][0]); acc[0][1] = fmaf(a.x, b.y, acc[0][1]);
        acc[0][2] = fmaf(a.x, b.z, acc[0][2]); acc[0][3] = fmaf(a.x, b.w, acc[0][3]);
        acc[1][0] = fmaf(a.y, b.x, acc[1][0]); acc[1][1] = fmaf(a.y, b.y, acc[1][1]);
        acc[1][2] = fmaf(a.y, b.z, acc[1][2]); acc[1][3] = fmaf(a.y, b.w, acc[1][3]);
        acc[2][0] = fmaf(a.z, b.x, acc[2][0]); acc[2][1] = fmaf(a.z, b.y, acc[2][1]);
        acc[2][2] = fmaf(a.z, b.z, acc[2][2]); acc[2][3] = fmaf(a.z, b.w, acc[2][3]);
        acc[3][0] = fmaf(a.w, b.x, acc[3][0]); acc[3][1] = fmaf(a.w, b.y, acc[3][1]);
        acc[3][2] = fmaf(a.w, b.z, acc[3][2]); acc[3][3] = fmaf(a.w, b.w, acc[3][3]);
    }
#pragma unroll
    for (int i = 0; i < 4; i++) {
#pragma unroll
        for (int j = 0; j < 4; j++) {
            int k = k0 + ty * 4 + i, n = n0 + tx * 4 + j;
            if (k < KSEL && n < NPTS)
                W[((size_t)k * NG + g) * NPTS + n] = acc[i][j] * 0.125f;
        }
    }
}

// ======= fused gate + softmax: W[k,g,n] = gate*exp(aff) / sum_n =======
__global__ __launch_bounds__(512) void gatesm_kernel(const float* __restrict__ bboxes,
                                                     const float* __restrict__ Wg,
                                                     const float* __restrict__ bg,
                                                     float* __restrict__ W)
{
    const int k = blockIdx.x;
    const int tid = threadIdx.x;
    __shared__ float sWg[NG][64];
    __shared__ float sbg[NG];
    __shared__ float qb[4];
    __shared__ float tot[NG];
    for (int i = tid; i < NG * 64; i += 512) sWg[i >> 6][i & 63] = Wg[i];
    if (tid < NG) { sbg[tid] = bg[tid]; tot[tid] = 0.f; }
    if (tid == 0) {
        int qi = g_idx[k];
        float x1 = bboxes[qi * 4 + 0], y1 = bboxes[qi * 4 + 1];
        float x2 = bboxes[qi * 4 + 2], y2 = bboxes[qi * 4 + 3];
        qb[0] = x2 - x1 + 1.f; qb[1] = y2 - y1 + 1.f;
        qb[2] = 0.5f * (x1 + x2); qb[3] = 0.5f * (y1 + y2);
    }
    __syncthreads();
    const float dimmat[8] = { 1.0f, 2.3713737057f, 5.6234132519f, 13.3352143216f,
                              31.6227766017f, 74.9894209332f, 177.8279410039f, 421.6965034286f };
    float gsum[NG];
#pragma unroll
    for (int g = 0; g < NG; g++) gsum[g] = 0.f;
    const float w = qb[0], h = qb[1], cx = qb[2], cy = qb[3];
    const size_t kbase = (size_t)k * NG * NPTS;

    for (int n = tid; n < NPTS; n += 512) {
        float4 bb = *(const float4*)(bboxes + (size_t)n * 4);
        float wr = bb.z - bb.x + 1.f, hr = bb.w - bb.y + 1.f;
        float cxr = 0.5f * (bb.x + bb.z), cyr = 0.5f * (bb.y + bb.w);
        float pos[4];
        pos[0] = logf(fabsf((cx - cxr) / w) + 1e-3f);
        pos[1] = logf(fabsf((cy - cyr) / h) + 1e-3f);
        pos[2] = logf(w / wr);
        pos[3] = logf(h / hr);
        float gw[NG];
#pragma unroll
        for (int g = 0; g < NG; g++) gw[g] = sbg[g];
#pragma unroll
        for (int c = 0; c < 4; c++) {
            float p100 = pos[c] * 100.f;
#pragma unroll
            for (int f = 0; f < 8; f++) {
                float arg = p100 / dimmat[f];
                float s, co;
                sincosf(arg, &s, &co);
#pragma unroll
                for (int g = 0; g < NG; g++) {
                    gw[g] = fmaf(sWg[g][c * 16 + f],     s,  gw[g]);
                    gw[g] = fmaf(sWg[g][c * 16 + 8 + f], co, gw[g]);
                }
            }
        }
#pragma unroll
        for (int g = 0; g < NG; g++) {
            size_t idx = kbase + (size_t)g * NPTS + n;
            float aw = fmaxf(gw[g], 0.f) + 1e-6f;
            float t = aw * __expf(W[idx]);
            W[idx] = t;
            gsum[g] += t;
        }
    }
#pragma unroll
    for (int g = 0; g < NG; g++) {
        float s = gsum[g];
#pragma unroll
        for (int o = 16; o > 0; o >>= 1) s += __shfl_down_sync(0xffffffffu, s, o);
        if ((tid & 31) == 0) atomicAdd(&tot[g], s);
    }
    __syncthreads();
    float inv[NG];
#pragma unroll
    for (int g = 0; g < NG; g++) inv[g] = 1.0f / tot[g];
    for (int n = tid; n < NPTS; n += 512) {
#pragma unroll
        for (int g = 0; g < NG; g++) {
            size_t idx = kbase + (size_t)g * NPTS + n;
            W[idx] *= inv[g];
        }
    }
}

// ---------------- out[k, g*64+o] = sum_n soft[k,g,n] * V[n,g,o] + bv ----------------
__global__ __launch_bounds__(256) void out_kernel(const float* __restrict__ W,
                                                  const float* __restrict__ V,
                                                  const float* __restrict__ bv,
                                                  float* __restrict__ out)
{
    int g  = blockIdx.y;
    int k0 = blockIdx.x * 32;
    __shared__ float Ss[32][64];
    __shared__ float Vs[64][65];
    int tid = threadIdx.x;
    int o  = tid & 63;
    int ks = tid >> 6;
    float acc[8] = {};
    for (int n0 = 0; n0 < NPTS; n0 += 64) {
#pragma unroll
        for (int it = 0; it < 8; it++) {
            int idx = tid + it * 256;
            int r = idx >> 6, c = idx & 63;
            int kq = k0 + r, nn = n0 + c;
            Ss[r][c] = (kq < KSEL && nn < NPTS) ? W[((size_t)kq * NG + g) * NPTS + nn] : 0.f;
        }
#pragma unroll
        for (int it = 0; it < 16; it++) {
            int idx = tid + it * 256;
            int r = idx >> 6, c = idx & 63;
            int nn = n0 + r;
            Vs[r][c] = (nn < NPTS) ? V[(size_t)nn * DIM + g * DG + c] : 0.f;
        }
        __syncthreads();
#pragma unroll
        for (int n = 0; n < 64; n++) {
            float v = Vs[n][o];
#pragma unroll
            for (int i = 0; i < 8; i++) acc[i] = fmaf(Ss[ks * 8 + i][n], v, acc[i]);
        }
        __syncthreads();
    }
#pragma unroll
    for (int i = 0; i < 8; i++) {
        int kq = k0 + ks * 8 + i;
        if (kq < KSEL) out[(size_t)kq * DIM + g * DG + o] = acc[i] + bv[g * DG + o];
    }
}

// ---------------- launch ----------------
extern "C" void kernel_launch(void* const* d_in, const int* in_sizes, int n_in,
                              void* d_out, int out_size)
{
    (void)in_sizes; (void)n_in; (void)out_size;
    const float* merged = (const float*)d_in[0];
    const float* bboxes = (const float*)d_in[1];
    const float* Wq     = (const float*)d_in[2];
    const float* bq     = (const float*)d_in[3];
    const float* Wk     = (const float*)d_in[4];
    const float* bk     = (const float*)d_in[5];
    const float* Wg     = (const float*)d_in[6];
    const float* bg     = (const float*)d_in[7];
    const float* Wv     = (const float*)d_in[8];
    const float* bv     = (const float*)d_in[9];
    float* out = (float*)d_out;

    float *p_q, *p_kk, *p_V, *p_W;
    int* p_idx;
    __half *p_Xa, *p_Wqs, *p_Wks, *p_Wvs;
    cudaGetSymbolAddress((void**)&p_q,   g_q);
    cudaGetSymbolAddress((void**)&p_kk,  g_kk);
    cudaGetSymbolAddress((void**)&p_V,   g_V);
    cudaGetSymbolAddress((void**)&p_W,   g_W);
    cudaGetSymbolAddress((void**)&p_idx, g_idx);
    cudaGetSymbolAddress((void**)&p_Xa,  g_Xa);
    cudaGetSymbolAddress((void**)&p_Wqs, g_Wqs);
    cudaGetSymbolAddress((void**)&p_Wks, g_Wks);
    cudaGetSymbolAddress((void**)&p_Wvs, g_Wvs);

    cudaFuncSetAttribute(mma_gemm_kernel, cudaFuncAttributeMaxDynamicSharedMemorySize, GSMEM);

    // 0) fp16 3-term splits (X A-pattern; all three weights in one launch)
    splitX_kernel<<<(NPTS * DIM + 255) / 256, 256>>>(merged);
    splitW_kernel<<<dim3((DIM * DIM + 255) / 256, 3), 256>>>(Wq, Wk, Wv);

    // 1) norms + Drec via fp32 SIMT 128x128/8x8 (bit-identical k-order)
    norms_kernel<<<NPTS, 256>>>(merged);
    drec128_kernel<<<dim3(47, 47), 256>>>(merged);

    // 2) sequential greedy FPS
    fps_kernel<<<1, 1024>>>();

    // 3) projections via proven HMMA (q gathered, kk, V)
    mma_gemm_kernel<<<dim3(8, 3),  256, GSMEM>>>(p_Xa, p_Wqs, p_q,  KSEL, DIM, bq, p_idx);
    mma_gemm_kernel<<<dim3(8, 47), 256, GSMEM>>>(p_Xa, p_Wks, p_kk, NPTS, DIM, bk, nullptr);
    mma_gemm_kernel<<<dim3(8, 47), 256, GSMEM>>>(p_Xa, p_Wvs, p_V,  NPTS, DIM, nullptr, nullptr);

    // 4) attention: aff logits, fused gate+softmax, weighted sum
    aff_kernel<<<dim3(47, 10, NG), 256>>>(p_q, p_kk, p_W);
    gatesm_kernel<<<KSEL, 512>>>(bboxes, Wg, bg, p_W);
    out_kernel<<<dim3(10, NG), 256>>>(p_W, p_V, bv, out);
}

// round 17
// speedup vs baseline: 1.7801x; 1.0362x over previous
#include <cuda_runtime.h>
#include <cuda_fp16.h>
#include <math.h>
#include <math_constants.h>
#include <stdint.h>

#define NPTS 6000
#define DIM  1024
#define K3   3072
#define NG   16
#define DG   64
#define KSEL 300

// gate lookup table: 4 coords x 24577 nodes x 16 groups
#define TBN   24577
#define PMIN  (-7.0f)
#define TDELTA 0.00048828125f     // 2^-11  (span 12.0 over 24576 intervals)
#define TINVD  2048.0f

// ---------------- scratch (device globals; no allocation allowed) ----------------
static __device__ float g_norms[NPTS];
static __device__ float g_Drec[(size_t)NPTS * NPTS];          // 144 MB
static __device__ int   g_idx[KSEL];
static __device__ float g_q[KSEL * DIM];
static __device__ float g_kk[(size_t)NPTS * DIM];
static __device__ float g_V[(size_t)NPTS * DIM];
static __device__ float g_W[(size_t)KSEL * NG * NPTS];        // 115 MB logits/soft
static __device__ float g_tot[KSEL * NG];
static __device__ float g_tab[4][TBN][NG];                    // 6.3 MB gate table
static __device__ __half g_Xa[(size_t)NPTS * K3];             // [h | l | h]
static __device__ __half g_Wqs[(size_t)DIM * K3];             // [h | h | l]
static __device__ __half g_Wks[(size_t)DIM * K3];
static __device__ __half g_Wvs[(size_t)DIM * K3];

__device__ __forceinline__ uint32_t smem_u32(const void* p) {
    uint32_t a;
    asm("{ .reg .u64 t; cvta.to.shared.u64 t, %1; cvt.u32.u64 %0, t; }" : "=r"(a) : "l"(p));
    return a;
}
#define CP_ASYNC16(dst, src) \
    asm volatile("cp.async.cg.shared.global [%0], [%1], 16;" :: "r"(dst), "l"(src))
#define CP_COMMIT() asm volatile("cp.async.commit_group;")
#define CP_WAIT1()  asm volatile("cp.async.wait_group 1;")
#define CP_WAIT0()  asm volatile("cp.async.wait_group 0;")
#define LDMATRIX_X4(r0, r1, r2, r3, a) \
    asm volatile("ldmatrix.sync.aligned.m8n8.x4.shared.b16 {%0,%1,%2,%3}, [%4];" \
        : "=r"(r0), "=r"(r1), "=r"(r2), "=r"(r3) : "r"(a))
#define MMA16816(c, a, b0, b1) \
    asm volatile("mma.sync.aligned.m16n8k16.row.col.f32.f16.f16.f32 " \
        "{%0,%1,%2,%3}, {%4,%5,%6,%7}, {%8,%9}, {%0,%1,%2,%3};" \
        : "+f"((c)[0]), "+f"((c)[1]), "+f"((c)[2]), "+f"((c)[3]) \
        : "r"((a)[0]), "r"((a)[1]), "r"((a)[2]), "r"((a)[3]), "r"(b0), "r"(b1))

// ---------------- 3-term fp16 split for X (A-pattern [h|l|h]) -------------------
__global__ __launch_bounds__(256) void splitX_kernel(const float* __restrict__ X) {
    size_t i = (size_t)blockIdx.x * 256 + threadIdx.x;
    if (i >= (size_t)NPTS * DIM) return;
    size_t r = i / DIM, c = i % DIM;
    float x = X[i];
    __half h = __float2half(x);
    __half l = __float2half(x - __half2float(h));
    g_Xa[r * K3 + c]            = h;
    g_Xa[r * K3 + DIM + c]      = l;
    g_Xa[r * K3 + 2 * DIM + c]  = h;
}

// ---------------- merged weight split (B-pattern [h|h|l]) for Wq/Wk/Wv ----------
__global__ __launch_bounds__(256) void splitW_kernel(const float* __restrict__ Wq,
                                                     const float* __restrict__ Wk,
                                                     const float* __restrict__ Wv) {
    size_t i = (size_t)blockIdx.x * 256 + threadIdx.x;
    if (i >= (size_t)DIM * DIM) return;
    const float* src = (blockIdx.y == 0) ? Wq : (blockIdx.y == 1) ? Wk : Wv;
    __half* dst = (blockIdx.y == 0) ? g_Wqs : (blockIdx.y == 1) ? g_Wks : g_Wvs;
    size_t r = i / DIM, c = i % DIM;
    float x = src[i];
    __half h = __float2half(x);
    __half l = __float2half(x - __half2float(h));
    dst[r * K3 + c]            = h;
    dst[r * K3 + DIM + c]      = h;
    dst[r * K3 + 2 * DIM + c]  = l;
}

// ---------------- gate table build: G[c][node][g] -------------------------------
__global__ __launch_bounds__(256) void tabbuild_kernel(const float* __restrict__ Wg) {
    const int c = blockIdx.y;
    const int node = blockIdx.x * 256 + threadIdx.x;
    if (node >= TBN) return;
    const float dimmat[8] = { 1.0f, 2.3713737057f, 5.6234132519f, 13.3352143216f,
                              31.6227766017f, 74.9894209332f, 177.8279410039f, 421.6965034286f };
    float p100 = (PMIN + node * TDELTA) * 100.f;
    float acc[NG];
#pragma unroll
    for (int g = 0; g < NG; g++) acc[g] = 0.f;
#pragma unroll
    for (int f = 0; f < 8; f++) {
        float s, co;
        sincosf(p100 / dimmat[f], &s, &co);
#pragma unroll
        for (int g = 0; g < NG; g++) {
            acc[g] = fmaf(Wg[g * 64 + c * 16 + f],     s,  acc[g]);
            acc[g] = fmaf(Wg[g * 64 + c * 16 + 8 + f], co, acc[g]);
        }
    }
#pragma unroll
    for (int g = 0; g < NG; g++) g_tab[c][node][g] = acc[g];
}

// ---------------- row squared-norms ----------------
__global__ __launch_bounds__(256) void norms_kernel(const float* __restrict__ X) {
    int r = blockIdx.x;
    const float* x = X + (size_t)r * DIM;
    float s = 0.f;
    for (int c = threadIdx.x; c < DIM; c += 256) { float v = x[c]; s = fmaf(v, v, s); }
    __shared__ float sred[8];
    for (int o = 16; o > 0; o >>= 1) s += __shfl_down_sync(0xffffffffu, s, o);
    if ((threadIdx.x & 31) == 0) sred[threadIdx.x >> 5] = s;
    __syncthreads();
    if (threadIdx.x == 0) {
        float t = 0.f;
        for (int i = 0; i < 8; i++) t += sred[i];
        g_norms[r] = t;
    }
}

// ====== symmetric fp32 Drec GEMM, 128x128 block, 8x8 thread tile ======
#define DBK 16
__global__ __launch_bounds__(256) void drec128_kernel(const float* __restrict__ A)
{
    const int bi = blockIdx.y, bj = blockIdx.x;
    if (bj < bi) return;
    __shared__ float As[DBK][128];
    __shared__ float Bs[DBK][128];
    const int tid = threadIdx.x;
    const int bm = bi * 128, bn = bj * 128;
    const int lrow = tid & 127;
    const int lk = (tid >> 7) * 8;
    const int tx = tid & 15, ty = tid >> 4;

    int arow = bm + lrow; if (arow > NPTS - 1) arow = NPTS - 1;
    int brow = bn + lrow; if (brow > NPTS - 1) brow = NPTS - 1;
    const float* apt = A + (size_t)arow * DIM + lk;
    const float* bpt = A + (size_t)brow * DIM + lk;

    float4 pa0 = *(const float4*)(apt);
    float4 pa1 = *(const float4*)(apt + 4);
    float4 pb0 = *(const float4*)(bpt);
    float4 pb1 = *(const float4*)(bpt + 4);

    float acc[2][2][4][4] = {};

    for (int k0 = 0; k0 < DIM; k0 += DBK) {
        As[lk + 0][lrow] = pa0.x; As[lk + 1][lrow] = pa0.y; As[lk + 2][lrow] = pa0.z; As[lk + 3][lrow] = pa0.w;
        As[lk + 4][lrow] = pa1.x; As[lk + 5][lrow] = pa1.y; As[lk + 6][lrow] = pa1.z; As[lk + 7][lrow] = pa1.w;
        Bs[lk + 0][lrow] = pb0.x; Bs[lk + 1][lrow] = pb0.y; Bs[lk + 2][lrow] = pb0.z; Bs[lk + 3][lrow] = pb0.w;
        Bs[lk + 4][lrow] = pb1.x; Bs[lk + 5][lrow] = pb1.y; Bs[lk + 6][lrow] = pb1.z; Bs[lk + 7][lrow] = pb1.w;
        __syncthreads();
        if (k0 + DBK < DIM) {
            pa0 = *(const float4*)(apt + k0 + DBK);
            pa1 = *(const float4*)(apt + k0 + DBK + 4);
            pb0 = *(const float4*)(bpt + k0 + DBK);
            pb1 = *(const float4*)(bpt + k0 + DBK + 4);
        }
#pragma unroll
        for (int kk = 0; kk < DBK; kk++) {
            float4 a0 = *(const float4*)&As[kk][ty * 4];
            float4 a1 = *(const float4*)&As[kk][64 + ty * 4];
            float4 b0 = *(const float4*)&Bs[kk][tx * 4];
            float4 b1 = *(const float4*)&Bs[kk][64 + tx * 4];
            const float ar[2][4] = { {a0.x, a0.y, a0.z, a0.w}, {a1.x, a1.y, a1.z, a1.w} };
            const float br[2][4] = { {b0.x, b0.y, b0.z, b0.w}, {b1.x, b1.y, b1.z, b1.w} };
#pragma unroll
            for (int ih = 0; ih < 2; ih++)
#pragma unroll
                for (int i = 0; i < 4; i++)
#pragma unroll
                    for (int jh = 0; jh < 2; jh++)
#pragma unroll
                        for (int j = 0; j < 4; j++)
                            acc[ih][jh][i][j] = fmaf(ar[ih][i], br[jh][j], acc[ih][jh][i][j]);
        }
        __syncthreads();
    }

#pragma unroll
    for (int ih = 0; ih < 2; ih++) {
#pragma unroll
        for (int i = 0; i < 4; i++) {
            int m = bm + ih * 64 + ty * 4 + i;
            if (m >= NPTS) continue;
            float nm = g_norms[m];
#pragma unroll
            for (int jh = 0; jh < 2; jh++) {
#pragma unroll
                for (int j = 0; j < 4; j++) {
                    int n = bn + jh * 64 + tx * 4 + j;
                    if (n < NPTS && n >= m) {
                        float sq = fmaxf(nm + g_norms[n] - 2.f * acc[ih][jh][i][j], 0.f);
                        float v = (m == n) ? CUDART_INF_F : (1.0f / sqrtf(sq));
                        g_Drec[(size_t)m * NPTS + n] = v;
                        if (n > m) g_Drec[(size_t)n * NPTS + m] = v;
                    }
                }
            }
        }
    }
}

// =============== fp16 HMMA GEMM (R8-proven, projections only) ===============
#define BK 64
#define NC (K3 / BK)
#define SROW 144
#define STAGE_BYTES (2 * 128 * SROW)
#define GSMEM (2 * STAGE_BYTES)

__global__ __launch_bounds__(256) void mma_gemm_kernel(
    const __half* __restrict__ A, const __half* __restrict__ B,
    float* __restrict__ C, int M, int Nn,
    const float* __restrict__ bias, const int* __restrict__ rowIdx)
{
    extern __shared__ char smem[];
    const uint32_t sb = smem_u32(smem);
    const int tid = threadIdx.x;
    const int wid = tid >> 5;
    const int lid = tid & 31;
    const int bm = blockIdx.y * 128;
    const int bn = blockIdx.x * 128;

    const __half* gsrc[8];
    uint32_t sdst[8];
#pragma unroll
    for (int i = 0; i < 8; i++) {
        int u = tid + i * 256;
        int mat = u >> 10;
        int r = (u >> 3) & 127;
        int q = u & 7;
        int grow;
        if (mat == 0) {
            grow = bm + r; if (grow > M - 1) grow = M - 1;
            if (rowIdx) grow = rowIdx[grow];
            gsrc[i] = A + (size_t)grow * K3 + q * 8;
        } else {
            grow = bn + r; if (grow > Nn - 1) grow = Nn - 1;
            gsrc[i] = B + (size_t)grow * K3 + q * 8;
        }
        sdst[i] = sb + (uint32_t)(mat * 128 * SROW + r * SROW + q * 16);
    }

#pragma unroll
    for (int i = 0; i < 8; i++) CP_ASYNC16(sdst[i], gsrc[i]);
    CP_COMMIT();
#pragma unroll
    for (int i = 0; i < 8; i++) CP_ASYNC16(sdst[i] + STAGE_BYTES, gsrc[i] + BK);
    CP_COMMIT();

    const int wm = (wid >> 2) * 64;
    const int wn = (wid & 3) * 32;
    float c[4][4][4] = {};

    const uint32_t aAddrBase = sb + (uint32_t)((wm + (lid & 15)) * SROW + (lid >> 4) * 16);
    const uint32_t bAddrBase = sb + (uint32_t)(128 * SROW + (wn + (lid >> 4) * 8 + (lid & 7)) * SROW + ((lid >> 3) & 1) * 16);

    for (int kc = 0; kc < NC; kc++) {
        if (kc == NC - 1) { CP_WAIT0(); } else { CP_WAIT1(); }
        __syncthreads();
        const uint32_t stg = (uint32_t)(kc & 1) * STAGE_BYTES;
#pragma unroll
        for (int ks = 0; ks < 4; ks++) {
            const uint32_t kb = ks * 32;
            uint32_t a[4][4];
#pragma unroll
            for (int mt = 0; mt < 4; mt++)
                LDMATRIX_X4(a[mt][0], a[mt][1], a[mt][2], a[mt][3],
                            aAddrBase + stg + mt * (16 * SROW) + kb);
#pragma unroll
            for (int nt2 = 0; nt2 < 2; nt2++) {
                uint32_t b0, b1, b2, b3;
                LDMATRIX_X4(b0, b1, b2, b3, bAddrBase + stg + nt2 * (16 * SROW) + kb);
#pragma unroll
                for (int mt = 0; mt < 4; mt++) {
                    MMA16816(c[mt][nt2 * 2 + 0], a[mt], b0, b1);
                    MMA16816(c[mt][nt2 * 2 + 1], a[mt], b2, b3);
                }
            }
        }
        __syncthreads();
        if (kc + 2 < NC) {
#pragma unroll
            for (int i = 0; i < 8; i++)
                CP_ASYNC16(sdst[i] + stg, gsrc[i] + (kc + 2) * BK);
            CP_COMMIT();
        }
    }

    const int er = lid >> 2;
    const int ec = (lid & 3) * 2;
#pragma unroll
    for (int mt = 0; mt < 4; mt++) {
#pragma unroll
        for (int nt = 0; nt < 4; nt++) {
#pragma unroll
            for (int half = 0; half < 2; half++) {
                int m = bm + wm + mt * 16 + er + half * 8;
                int n = bn + wn + nt * 8 + ec;
                if (m < M && n < Nn) {
                    float v0 = c[mt][nt][half * 2 + 0];
                    float v1 = c[mt][nt][half * 2 + 1];
                    if (bias) { v0 += bias[n]; v1 += bias[n + 1]; }
                    *(float2*)&C[(size_t)m * Nn + n] = make_float2(v0, v1);
                }
            }
        }
    }
}

// ---------------- sequential greedy FPS (single CTA, float4 rows) ----------------
__global__ __launch_bounds__(1024) void fps_kernel()
{
    const int tid = threadIdx.x;
    const bool v1 = (tid < 476);
    const int b0 = tid * 4;
    const int b1 = 4096 + tid * 4;
    float4 d0 = *(const float4*)&g_Drec[b0];
    float4 d1 = v1 ? *(const float4*)&g_Drec[b1]
                   : make_float4(CUDART_INF_F, CUDART_INF_F, CUDART_INF_F, CUDART_INF_F);
    if (tid == 0) g_idx[0] = 0;
    __shared__ float swv[32];
    __shared__ int   swi[32];
    __shared__ int   sbest;
    for (int it = 1; it < KSEL; it++) {
        float bv = d0.x; int bi = b0;
        if (d0.y < bv) { bv = d0.y; bi = b0 + 1; }
        if (d0.z < bv) { bv = d0.z; bi = b0 + 2; }
        if (d0.w < bv) { bv = d0.w; bi = b0 + 3; }
        if (d1.x < bv) { bv = d1.x; bi = b1; }
        if (d1.y < bv) { bv = d1.y; bi = b1 + 1; }
        if (d1.z < bv) { bv = d1.z; bi = b1 + 2; }
        if (d1.w < bv) { bv = d1.w; bi = b1 + 3; }
#pragma unroll
        for (int o = 16; o > 0; o >>= 1) {
            float ov = __shfl_down_sync(0xffffffffu, bv, o);
            int   oi = __shfl_down_sync(0xffffffffu, bi, o);
            if (ov < bv || (ov == bv && oi < bi)) { bv = ov; bi = oi; }
        }
        int lane = tid & 31, wid = tid >> 5;
        if (lane == 0) { swv[wid] = bv; swi[wid] = bi; }
        __syncthreads();
        if (wid == 0) {
            bv = swv[lane]; bi = swi[lane];
#pragma unroll
            for (int o = 16; o > 0; o >>= 1) {
                float ov = __shfl_down_sync(0xffffffffu, bv, o);
                int   oi = __shfl_down_sync(0xffffffffu, bi, o);
                if (ov < bv || (ov == bv && oi < bi)) { bv = ov; bi = oi; }
            }
            if (lane == 0) { sbest = bi; g_idx[it] = bi; }
        }
        __syncthreads();
        const float* rowp = g_Drec + (size_t)sbest * NPTS;
        float4 r0 = *(const float4*)&rowp[b0];
        d0.x += r0.x; d0.y += r0.y; d0.z += r0.z; d0.w += r0.w;
        if (v1) {
            float4 r1 = *(const float4*)&rowp[b1];
            d1.x += r1.x; d1.y += r1.y; d1.z += r1.z; d1.w += r1.w;
        }
    }
}

// ---------------- aff[k,g,n] = (q_kg · kk_ng) / 8 ----------------
__global__ __launch_bounds__(256) void aff_kernel(const float* __restrict__ q,
                                                  const float* __restrict__ kk,
                                                  float* __restrict__ W)
{
    int g  = blockIdx.z;
    int k0 = blockIdx.y * 32;
    int n0 = blockIdx.x * 128;
    __shared__ float Qs[DG][32];
    __shared__ float Ks[DG][128];
    int tid = threadIdx.x;
#pragma unroll
    for (int it = 0; it < 2; it++) {
        int idx = tid + it * 256;
        int r = idx >> 4, c4 = (idx & 15) * 4;
        float4 v = make_float4(0.f, 0.f, 0.f, 0.f);
        if (k0 + r < KSEL) v = *(const float4*)(q + (size_t)(k0 + r) * DIM + g * DG + c4);
        Qs[c4 + 0][r] = v.x; Qs[c4 + 1][r] = v.y; Qs[c4 + 2][r] = v.z; Qs[c4 + 3][r] = v.w;
    }
#pragma unroll
    for (int it = 0; it < 8; it++) {
        int idx = tid + it * 256;
        int r = idx >> 4, c4 = (idx & 15) * 4;
        float4 v = make_float4(0.f, 0.f, 0.f, 0.f);
        if (n0 + r < NPTS) v = *(const float4*)(kk + (size_t)(n0 + r) * DIM + g * DG + c4);
        Ks[c4 + 0][r] = v.x; Ks[c4 + 1][r] = v.y; Ks[c4 + 2][r] = v.z; Ks[c4 + 3][r] = v.w;
    }
    __syncthreads();
    int tx = tid & 31;
    int ty = tid >> 5;
    float acc[4][4] = {};
#pragma unroll 16
    for (int d = 0; d < DG; d++) {
        float4 a = *(const float4*)&Qs[d][ty * 4];
        float4 b = *(const float4*)&Ks[d][tx * 4];
        acc[0][0] = fmaf(a.x, b.x, acc[0][0]); acc[0][1] = fmaf(a.x, b.y, acc[0][1]);
        acc[0][2] = fmaf(a.x, b.z, acc[0][2]); acc[0][3] = fmaf(a.x, b.w, acc[0][3]);
        acc[1][0] = fmaf(a.y, b.x, acc[1][0]); acc[1][1] = fmaf(a.y, b.y, acc[1][1]);
        acc[1][2] = fmaf(a.y, b.z, acc[1][2]); acc[1][3] = fmaf(a.y, b.w, acc[1][3]);
        acc[2][0] = fmaf(a.z, b.x, acc[2][0]); acc[2][1] = fmaf(a.z, b.y, acc[2][1]);
        acc[2][2] = fmaf(a.z, b.z, acc[2][2]); acc[2][3] = fmaf(a.z, b.w, acc[2][3]);
        acc[3][0] = fmaf(a.w, b.x, acc[3][0]); acc[3][1] = fmaf(a.w, b.y, acc[3][1]);
        acc[3][2] = fmaf(a.w, b.z, acc[3][2]); acc[3][3] = fmaf(a.w, b.w, acc[3][3]);
    }
#pragma unroll
    for (int i = 0; i < 4; i++) {
#pragma unroll
        for (int j = 0; j < 4; j++) {
            int k = k0 + ty * 4 + i, n = n0 + tx * 4 + j;
            if (k < KSEL && n < NPTS)
                W[((size_t)k * NG + g) * NPTS + n] = acc[i][j] * 0.125f;
        }
    }
}

// ======= gate (table interp) + exp: W = (relu(gate)+1e-6)*exp(aff); tot stored =======
__global__ __launch_bounds__(512) void gatesm_kernel(const float* __restrict__ bboxes,
                                                     const float* __restrict__ bg,
                                                     float* __restrict__ W)
{
    const int k = blockIdx.x;
    const int tid = threadIdx.x;
    __shared__ float sbg[NG];
    __shared__ float qb[4];
    __shared__ float tot[NG];
    if (tid < NG) { sbg[tid] = bg[tid]; tot[tid] = 0.f; }
    if (tid == 0) {
        int qi = g_idx[k];
        float x1 = bboxes[qi * 4 + 0], y1 = bboxes[qi * 4 + 1];
        float x2 = bboxes[qi * 4 + 2], y2 = bboxes[qi * 4 + 3];
        qb[0] = x2 - x1 + 1.f; qb[1] = y2 - y1 + 1.f;
        qb[2] = 0.5f * (x1 + x2); qb[3] = 0.5f * (y1 + y2);
    }
    __syncthreads();
    float gsum[NG];
#pragma unroll
    for (int g = 0; g < NG; g++) gsum[g] = 0.f;
    const float w = qb[0], h = qb[1], cx = qb[2], cy = qb[3];
    const size_t kbase = (size_t)k * NG * NPTS;

    for (int n = tid; n < NPTS; n += 512) {
        float4 bb = *(const float4*)(bboxes + (size_t)n * 4);
        float wr = bb.z - bb.x + 1.f, hr = bb.w - bb.y + 1.f;
        float cxr = 0.5f * (bb.x + bb.z), cyr = 0.5f * (bb.y + bb.w);
        float pos[4];
        pos[0] = logf(fabsf((cx - cxr) / w) + 1e-3f);
        pos[1] = logf(fabsf((cy - cyr) / h) + 1e-3f);
        pos[2] = logf(w / wr);
        pos[3] = logf(h / hr);
        float gw[NG];
#pragma unroll
        for (int g = 0; g < NG; g++) gw[g] = sbg[g];
#pragma unroll
        for (int c = 0; c < 4; c++) {
            float p = fminf(fmaxf(pos[c], PMIN), PMIN + 12.0f);
            float x = (p - PMIN) * TINVD;
            int i0 = (int)x;
            if (i0 > TBN - 2) i0 = TBN - 2;
            float fr = x - (float)i0;
            const float4* t0 = (const float4*)&g_tab[c][i0][0];
#pragma unroll
            for (int qd = 0; qd < 4; qd++) {
                float4 a = t0[qd];
                float4 b = t0[qd + 4];     // next node (contiguous 64B later)
                gw[qd * 4 + 0] += a.x + fr * (b.x - a.x);
                gw[qd * 4 + 1] += a.y + fr * (b.y - a.y);
                gw[qd * 4 + 2] += a.z + fr * (b.z - a.z);
                gw[qd * 4 + 3] += a.w + fr * (b.w - a.w);
            }
        }
#pragma unroll
        for (int g = 0; g < NG; g++) {
            size_t idx = kbase + (size_t)g * NPTS + n;
            float aw = fmaxf(gw[g], 0.f) + 1e-6f;
            float t = aw * __expf(W[idx]);
            W[idx] = t;
            gsum[g] += t;
        }
    }
#pragma unroll
    for (int g = 0; g < NG; g++) {
        float s = gsum[g];
#pragma unroll
        for (int o = 16; o > 0; o >>= 1) s += __shfl_down_sync(0xffffffffu, s, o);
        if ((tid & 31) == 0) atomicAdd(&tot[g], s);
    }
    __syncthreads();
    if (tid < NG) g_tot[k * NG + tid] = tot[tid];
}

// ---- out[k, g*64+o] = (sum_n t[k,g,n] * V[n,g,o]) / tot[k,g] + bv ----
__global__ __launch_bounds__(256) void out_kernel(const float* __restrict__ W,
                                                  const float* __restrict__ V,
                                                  const float* __restrict__ bv,
                                                  float* __restrict__ out)
{
    int g  = blockIdx.y;
    int k0 = blockIdx.x * 32;
    __shared__ float Ss[32][64];
    __shared__ float Vs[64][65];
    int tid = threadIdx.x;
    int o  = tid & 63;
    int ks = tid >> 6;
    float acc[8] = {};
    for (int n0 = 0; n0 < NPTS; n0 += 64) {
#pragma unroll
        for (int it = 0; it < 8; it++) {
            int idx = tid + it * 256;
            int r = idx >> 6, c = idx & 63;
            int kq = k0 + r, nn = n0 + c;
            Ss[r][c] = (kq < KSEL && nn < NPTS) ? W[((size_t)kq * NG + g) * NPTS + nn] : 0.f;
        }
#pragma unroll
        for (int it = 0; it < 16; it++) {
            int idx = tid + it * 256;
            int r = idx >> 6, c = idx & 63;
            int nn = n0 + r;
            Vs[r][c] = (nn < NPTS) ? V[(size_t)nn * DIM + g * DG + c] : 0.f;
        }
        __syncthreads();
#pragma unroll
        for (int n = 0; n < 64; n++) {
            float v = Vs[n][o];
#pragma unroll
            for (int i = 0; i < 8; i++) acc[i] = fmaf(Ss[ks * 8 + i][n], v, acc[i]);
        }
        __syncthreads();
    }
#pragma unroll
    for (int i = 0; i < 8; i++) {
        int kq = k0 + ks * 8 + i;
        if (kq < KSEL) {
            float inv = 1.0f / g_tot[kq * NG + g];
            out[(size_t)kq * DIM + g * DG + o] = acc[i] * inv + bv[g * DG + o];
        }
    }
}

// ---------------- launch ----------------
extern "C" void kernel_launch(void* const* d_in, const int* in_sizes, int n_in,
                              void* d_out, int out_size)
{
    (void)in_sizes; (void)n_in; (void)out_size;
    const float* merged = (const float*)d_in[0];
    const float* bboxes = (const float*)d_in[1];
    const float* Wq     = (const float*)d_in[2];
    const float* bq     = (const float*)d_in[3];
    const float* Wk     = (const float*)d_in[4];
    const float* bk     = (const float*)d_in[5];
    const float* Wg     = (const float*)d_in[6];
    const float* bg     = (const float*)d_in[7];
    const float* Wv     = (const float*)d_in[8];
    const float* bv     = (const float*)d_in[9];
    float* out = (float*)d_out;

    float *p_q, *p_kk, *p_V, *p_W;
    int* p_idx;
    __half *p_Xa, *p_Wqs, *p_Wks, *p_Wvs;
    cudaGetSymbolAddress((void**)&p_q,   g_q);
    cudaGetSymbolAddress((void**)&p_kk,  g_kk);
    cudaGetSymbolAddress((void**)&p_V,   g_V);
    cudaGetSymbolAddress((void**)&p_W,   g_W);
    cudaGetSymbolAddress((void**)&p_idx, g_idx);
    cudaGetSymbolAddress((void**)&p_Xa,  g_Xa);
    cudaGetSymbolAddress((void**)&p_Wqs, g_Wqs);
    cudaGetSymbolAddress((void**)&p_Wks, g_Wks);
    cudaGetSymbolAddress((void**)&p_Wvs, g_Wvs);

    cudaFuncSetAttribute(mma_gemm_kernel, cudaFuncAttributeMaxDynamicSharedMemorySize, GSMEM);

    // 0) fp16 3-term splits + gate lookup table
    splitX_kernel<<<(NPTS * DIM + 255) / 256, 256>>>(merged);
    splitW_kernel<<<dim3((DIM * DIM + 255) / 256, 3), 256>>>(Wq, Wk, Wv);
    tabbuild_kernel<<<dim3((TBN + 255) / 256, 4), 256>>>(Wg);

    // 1) norms + Drec via fp32 SIMT 128x128/8x8 (bit-identical)
    norms_kernel<<<NPTS, 256>>>(merged);
    drec128_kernel<<<dim3(47, 47), 256>>>(merged);

    // 2) sequential greedy FPS
    fps_kernel<<<1, 1024>>>();

    // 3) projections via proven HMMA (q gathered, kk, V)
    mma_gemm_kernel<<<dim3(8, 3),  256, GSMEM>>>(p_Xa, p_Wqs, p_q,  KSEL, DIM, bq, p_idx);
    mma_gemm_kernel<<<dim3(8, 47), 256, GSMEM>>>(p_Xa, p_Wks, p_kk, NPTS, DIM, bk, nullptr);
    mma_gemm_kernel<<<dim3(8, 47), 256, GSMEM>>>(p_Xa, p_Wvs, p_V,  NPTS, DIM, nullptr, nullptr);

    // 4) attention: aff logits, table-gate+exp (unnormalized), fused-normalize output
    aff_kernel<<<dim3(47, 10, NG), 256>>>(p_q, p_kk, p_W);
    gatesm_kernel<<<KSEL, 512>>>(bboxes, bg, p_W);
    out_kernel<<<dim3(10, NG), 256>>>(p_W, p_V, bv, out);
}